// round 14
// baseline (speedup 1.0000x reference)
#include <cuda_runtime.h>
#include <cuda_bf16.h>
#include <math.h>
#include <stdint.h>

// Problem constants
#define BATCH 16
#define CDIM 256
#define NDIM 4096          // 64*64 spatial
#define HEADS 4
#define ADIM 32
#define HID 128
#define QKVROWS 384        // 3*HID
#define NMEM 4
#define SCALE 0.17677669529663687f   // 32^-0.5
#define EPSN 1e-12f
#define NCHUNK 16          // ctx n-chunks
#define NPART  64          // NCHUNK*4 partials

// Scratch (device globals: allocation-free per harness rules)
__device__ float g_qkv[(size_t)BATCH * QKVROWS * NDIM]; // ~100MB
__device__ float g_kmax[BATCH * HEADS * ADIM];
__device__ float g_ctx[BATCH * HEADS * ADIM * ADIM];    // already * SCALE / Z
__device__ float g_ctx_part[(size_t)NPART * 64 * 1024]; // 16MB partials
__device__ float g_z_part[NPART * 64 * 32];
// Pre-split bf16 operands (k-contiguous rows)
__device__ __nv_bfloat16 g_wh[QKVROWS * CDIM];
__device__ __nv_bfloat16 g_wl[QKVROWS * CDIM];
__device__ __nv_bfloat16 g_xh[(size_t)BATCH * NDIM * CDIM];  // [b][n][c]
__device__ __nv_bfloat16 g_xl[(size_t)BATCH * NDIM * CDIM];
// Pre-split w_out (256 x 128)
__device__ __nv_bfloat16 g_woh[CDIM * HID];
__device__ __nv_bfloat16 g_wol[CDIM * HID];

// ---------------------------------------------------------------------------
__device__ __forceinline__ uint32_t smem_u32(const void* p) {
    uint32_t a;
    asm("{ .reg .u64 t; cvta.to.shared.u64 t, %1; cvt.u32.u64 %0, t; }" : "=r"(a) : "l"(p));
    return a;
}
#define CP_ASYNC16(saddr, gaddr) \
    asm volatile("cp.async.cg.shared.global [%0], [%1], 16;" :: "r"(saddr), "l"(gaddr) : "memory")
#define CP_COMMIT() asm volatile("cp.async.commit_group;" ::: "memory")
#define CP_WAIT(n)  asm volatile("cp.async.wait_group %0;" :: "n"(n) : "memory")

#define LDMATRIX_X4(r0, r1, r2, r3, addr) \
    asm volatile("ldmatrix.sync.aligned.m8n8.x4.shared.b16 {%0,%1,%2,%3}, [%4];" \
                 : "=r"(r0), "=r"(r1), "=r"(r2), "=r"(r3) : "r"(addr))
#define LDMATRIX_X2(r0, r1, addr) \
    asm volatile("ldmatrix.sync.aligned.m8n8.x2.shared.b16 {%0,%1}, [%2];" \
                 : "=r"(r0), "=r"(r1) : "r"(addr))
#define MMA_BF16(d0, d1, d2, d3, a0, a1, a2, a3, b0, b1) \
    asm volatile("mma.sync.aligned.m16n8k16.row.col.f32.bf16.bf16.f32 " \
                 "{%0,%1,%2,%3}, {%4,%5,%6,%7}, {%8,%9}, {%0,%1,%2,%3};" \
                 : "+f"(d0), "+f"(d1), "+f"(d2), "+f"(d3) \
                 : "r"(a0), "r"(a1), "r"(a2), "r"(a3), "r"(b0), "r"(b1))

// Deterministic float atomic max (int/uint ordering trick)
__device__ __forceinline__ void atomicMaxF(float* addr, float v) {
    if (v >= 0.f) atomicMax((int*)addr, __float_as_int(v));
    else          atomicMin((unsigned int*)addr, __float_as_uint(v));
}

// ---------------------------------------------------------------------------
// K0: seed g_kmax with memory-token maxima
// ---------------------------------------------------------------------------
__global__ __launch_bounds__(256) void k_kinit(const float* __restrict__ memkv) {
    int idx = blockIdx.x * 256 + threadIdx.x;   // b*128 + hd
    int hd = idx & 127;
    float mm = -INFINITY;
    #pragma unroll
    for (int j = 0; j < NMEM; j++) mm = fmaxf(mm, memkv[hd * NMEM + j]);
    g_kmax[idx] = mm;
}

// ---------------------------------------------------------------------------
// K1b: W*g -> bf16 hi/lo
// ---------------------------------------------------------------------------
__global__ __launch_bounds__(256) void k_wsplit(const float* __restrict__ wqkv,
                                                const float* __restrict__ gch) {
    int e = blockIdx.x * 256 + threadIdx.x;
    int k = e & 255;
    float w = wqkv[e] * gch[k];
    __nv_bfloat16 hi = __float2bfloat16(w);
    __nv_bfloat16 lo = __float2bfloat16(w - __bfloat162float(hi));
    g_wh[e] = hi;
    g_wl[e] = lo;
}

// ---------------------------------------------------------------------------
// K1d: w_out -> bf16 hi/lo
// ---------------------------------------------------------------------------
__global__ __launch_bounds__(256) void k_osplit(const float* __restrict__ wout) {
    int e = blockIdx.x * 256 + threadIdx.x;
    float w = wout[e];
    __nv_bfloat16 hi = __float2bfloat16(w);
    __nv_bfloat16 lo = __float2bfloat16(w - __bfloat162float(hi));
    g_woh[e] = hi;
    g_wol[e] = lo;
}

// ---------------------------------------------------------------------------
// K1: fused rnorm + transpose + bf16 split.  32-n tile: 34.9KB smem -> 6 CTAs/SM.
// ---------------------------------------------------------------------------
#define XP_NT  32
#define XP_PAD 33
#define XP_SMEM ((256 * XP_PAD + 8 * XP_NT + XP_NT) * 4)

__global__ __launch_bounds__(256) void k_xprep(const float* __restrict__ x) {
    extern __shared__ float xs[];
    float* red = xs + 256 * XP_PAD;   // [8][32]
    float* rns = red + 8 * XP_NT;     // [32]
    int n0 = blockIdx.x * XP_NT;
    int b  = blockIdx.y;
    int tid = threadIdx.x;
    const float* xb = x + (size_t)b * CDIM * NDIM + n0;

    #pragma unroll
    for (int t = 0; t < 8; t++) {
        int idx = tid + t * 256;
        int c = idx >> 3, nch = idx & 7;
        float4 v = *(const float4*)(xb + (size_t)c * NDIM + nch * 4);
        float* row = xs + c * XP_PAD + nch * 4;
        row[0] = v.x; row[1] = v.y; row[2] = v.z; row[3] = v.w;
    }
    __syncthreads();

    {
        int n = tid & 31, p = tid >> 5;
        const float* col = xs + (p * 32) * XP_PAD + n;
        float s = 0.f;
        #pragma unroll 8
        for (int i = 0; i < 32; i++) {
            float v = col[i * XP_PAD];
            s += v * v;
        }
        red[p * XP_NT + n] = s;
    }
    __syncthreads();
    if (tid < XP_NT) {
        float s = 0.f;
        #pragma unroll
        for (int p = 0; p < 8; p++) s += red[p * XP_NT + tid];
        rns[tid] = 16.0f / fmaxf(sqrtf(s), EPSN);
    }
    __syncthreads();

    #pragma unroll
    for (int t = 0; t < 16; t++) {
        int job = tid + t * 256;
        int cp = job & 127, n = job >> 7;
        float rn = rns[n];
        float v0 = xs[(2 * cp + 0) * XP_PAD + n] * rn;
        float v1 = xs[(2 * cp + 1) * XP_PAD + n] * rn;
        __nv_bfloat16 h0 = __float2bfloat16(v0);
        __nv_bfloat16 h1 = __float2bfloat16(v1);
        __nv_bfloat16 l0 = __float2bfloat16(v0 - __bfloat162float(h0));
        __nv_bfloat16 l1 = __float2bfloat16(v1 - __bfloat162float(h1));
        uint32_t hp = (uint32_t)*(uint16_t*)&h0 | ((uint32_t)*(uint16_t*)&h1 << 16);
        uint32_t lp = (uint32_t)*(uint16_t*)&l0 | ((uint32_t)*(uint16_t*)&l1 << 16);
        size_t o = ((size_t)b * NDIM + n0 + n) * CDIM + cp * 2;
        *(uint32_t*)&g_xh[o] = hp;
        *(uint32_t*)&g_xl[o] = lp;
    }
}

// ---------------------------------------------------------------------------
// K2: QKV GEMM via mma.sync bf16 (split-bf16, 3 terms).
// m_base selects the m-tile window; do_kmax enables the K-row atomicMax
// epilogue (K tile = m0 == 128).
// ---------------------------------------------------------------------------
#define RS 80
#define T_AH 0
#define T_AL 10240
#define T_BH 20480
#define T_BL 30720
#define STG  40960

__global__ __launch_bounds__(256) void k_qkv_mma(int m_base, int do_kmax) {
    extern __shared__ char smem[];
    uint32_t sb = smem_u32(smem);
    int tid = threadIdx.x;
    int lane = tid & 31, wid = tid >> 5;
    int wm = wid & 1, wn = wid >> 1;
    int m0 = m_base + blockIdx.x * 128;
    int n0 = blockIdx.y * 128;
    int b  = blockIdx.z;

    const __nv_bfloat16* xhb = g_xh + (size_t)b * NDIM * CDIM;
    const __nv_bfloat16* xlb = g_xl + (size_t)b * NDIM * CDIM;

    float acc[4][4][4];
    #pragma unroll
    for (int i = 0; i < 4; i++)
        #pragma unroll
        for (int j = 0; j < 4; j++)
            #pragma unroll
            for (int r = 0; r < 4; r++) acc[i][j][r] = 0.f;

    auto issue_stage = [&](int s) {
        int k0 = s * 32;
        uint32_t dst_base = sb + (s & 1) * STG;
        #pragma unroll
        for (int t = 0; t < 8; t++) {
            int idx = tid + t * 256;
            int tile = idx >> 9;
            int i = idx & 511;
            int row = i >> 2, pos = i & 3;
            uint32_t daddr = dst_base + tile * 10240 + row * RS + pos * 16;
            const __nv_bfloat16* src;
            if (tile == 0)      src = g_wh + (size_t)(m0 + row) * CDIM + k0 + pos * 8;
            else if (tile == 1) src = g_wl + (size_t)(m0 + row) * CDIM + k0 + pos * 8;
            else if (tile == 2) src = xhb + (size_t)(n0 + row) * CDIM + k0 + pos * 8;
            else                src = xlb + (size_t)(n0 + row) * CDIM + k0 + pos * 8;
            CP_ASYNC16(daddr, src);
        }
        CP_COMMIT();
    };

    issue_stage(0);
    for (int s = 0; s < 8; s++) {
        if (s + 1 < 8) {
            issue_stage(s + 1);
            CP_WAIT(1);
        } else {
            CP_WAIT(0);
        }
        __syncthreads();
        uint32_t buf = sb + (s & 1) * STG;

        #pragma unroll
        for (int ks = 0; ks < 2; ks++) {
            uint32_t ah[4][4], al[4][4], bh[4][2], bl[4][2];
            int akoff = (ks * 16 + (lane >> 4) * 8) * 2;
            int arow = (lane & 15);
            #pragma unroll
            for (int mi = 0; mi < 4; mi++) {
                int rb = wm * 64 + mi * 16 + arow;
                LDMATRIX_X4(ah[mi][0], ah[mi][1], ah[mi][2], ah[mi][3], buf + T_AH + rb * RS + akoff);
                LDMATRIX_X4(al[mi][0], al[mi][1], al[mi][2], al[mi][3], buf + T_AL + rb * RS + akoff);
            }
            int l = lane & 15;
            int bkoff = (ks * 16 + (l >> 3) * 8) * 2;
            int brow = l & 7;
            #pragma unroll
            for (int ni = 0; ni < 4; ni++) {
                int rb = wn * 32 + ni * 8 + brow;
                LDMATRIX_X2(bh[ni][0], bh[ni][1], buf + T_BH + rb * RS + bkoff);
                LDMATRIX_X2(bl[ni][0], bl[ni][1], buf + T_BL + rb * RS + bkoff);
            }
            #pragma unroll
            for (int mi = 0; mi < 4; mi++)
                #pragma unroll
                for (int ni = 0; ni < 4; ni++)
                    MMA_BF16(acc[mi][ni][0], acc[mi][ni][1], acc[mi][ni][2], acc[mi][ni][3],
                             ah[mi][0], ah[mi][1], ah[mi][2], ah[mi][3], bh[ni][0], bh[ni][1]);
            #pragma unroll
            for (int mi = 0; mi < 4; mi++)
                #pragma unroll
                for (int ni = 0; ni < 4; ni++)
                    MMA_BF16(acc[mi][ni][0], acc[mi][ni][1], acc[mi][ni][2], acc[mi][ni][3],
                             ah[mi][0], ah[mi][1], ah[mi][2], ah[mi][3], bl[ni][0], bl[ni][1]);
            #pragma unroll
            for (int mi = 0; mi < 4; mi++)
                #pragma unroll
                for (int ni = 0; ni < 4; ni++)
                    MMA_BF16(acc[mi][ni][0], acc[mi][ni][1], acc[mi][ni][2], acc[mi][ni][3],
                             al[mi][0], al[mi][1], al[mi][2], al[mi][3], bh[ni][0], bh[ni][1]);
        }
        __syncthreads();
    }

    float* outp = g_qkv + (size_t)b * QKVROWS * NDIM;
    int tr = lane >> 2, tc = (lane & 3) * 2;
    #pragma unroll
    for (int mi = 0; mi < 4; mi++) {
        #pragma unroll
        for (int ni = 0; ni < 4; ni++) {
            int o0 = m0 + wm * 64 + mi * 16 + tr;
            int nn = n0 + wn * 32 + ni * 8 + tc;
            float2 v0 = make_float2(acc[mi][ni][0], acc[mi][ni][1]);
            float2 v1 = make_float2(acc[mi][ni][2], acc[mi][ni][3]);
            *(float2*)(outp + (size_t)o0 * NDIM + nn)       = v0;
            *(float2*)(outp + (size_t)(o0 + 8) * NDIM + nn) = v1;
        }
    }

    if (do_kmax && m0 == 128) {
        #pragma unroll
        for (int mi = 0; mi < 4; mi++) {
            float mA = -INFINITY, mB = -INFINITY;
            #pragma unroll
            for (int ni = 0; ni < 4; ni++) {
                mA = fmaxf(mA, fmaxf(acc[mi][ni][0], acc[mi][ni][1]));
                mB = fmaxf(mB, fmaxf(acc[mi][ni][2], acc[mi][ni][3]));
            }
            mA = fmaxf(mA, __shfl_xor_sync(0xffffffffu, mA, 1));
            mA = fmaxf(mA, __shfl_xor_sync(0xffffffffu, mA, 2));
            mB = fmaxf(mB, __shfl_xor_sync(0xffffffffu, mB, 1));
            mB = fmaxf(mB, __shfl_xor_sync(0xffffffffu, mB, 2));
            if ((lane & 3) == 0) {
                int hd = wm * 64 + mi * 16 + tr;
                atomicMaxF(&g_kmax[b * 128 + hd], mA);
                atomicMaxF(&g_kmax[b * 128 + hd + 8], mB);
            }
        }
    }
}

// ---------------------------------------------------------------------------
// K3b (stage A): partial ctx over an n-chunk of 256, split 4-way in j.
// ---------------------------------------------------------------------------
__global__ __launch_bounds__(256) void k_ctx_part() {
    __shared__ float ks[32 * 129];
    __shared__ float vs[32 * 129];
    __shared__ float kml[32];
    int chunk = blockIdx.x;
    int bh = blockIdx.y;
    int b = bh >> 2, h = bh & 3;
    int tid = threadIdx.x;
    int jp = tid >> 6;
    int tile = tid & 63;
    int d0 = (tile & 7) * 4;
    int e0 = (tile >> 3) * 4;

    const float* base = g_qkv + (size_t)b * QKVROWS * NDIM;
    const float* kp = base + (size_t)(HID + h * ADIM) * NDIM;
    const float* vp = base + (size_t)(2 * HID + h * ADIM) * NDIM;

    if (tid < 32) kml[tid] = g_kmax[b * 128 + h * 32 + tid];
    __syncthreads();

    float acc[4][4];
    #pragma unroll
    for (int i = 0; i < 4; i++)
        #pragma unroll
        for (int m = 0; m < 4; m++) acc[i][m] = 0.f;
    float zacc[4] = {0.f, 0.f, 0.f, 0.f};

    for (int st = 0; st < 2; st++) {
        int n0 = chunk * 256 + st * 128;
        __syncthreads();
        #pragma unroll
        for (int f = tid; f < 1024; f += 256) {
            int r = f >> 5, c4 = (f & 31) * 4;
            float km = kml[r];
            float4 kv = *(const float4*)(kp + (size_t)r * NDIM + n0 + c4);
            ks[r * 129 + c4 + 0] = expf(kv.x - km);
            ks[r * 129 + c4 + 1] = expf(kv.y - km);
            ks[r * 129 + c4 + 2] = expf(kv.z - km);
            ks[r * 129 + c4 + 3] = expf(kv.w - km);
            float4 vv = *(const float4*)(vp + (size_t)r * NDIM + n0 + c4);
            vs[r * 129 + c4 + 0] = vv.x;
            vs[r * 129 + c4 + 1] = vv.y;
            vs[r * 129 + c4 + 2] = vv.z;
            vs[r * 129 + c4 + 3] = vv.w;
        }
        __syncthreads();
        #pragma unroll 4
        for (int jj = 0; jj < 32; jj++) {
            int j = jp * 32 + jj;
            float kd[4], vv[4];
            #pragma unroll
            for (int i = 0; i < 4; i++) kd[i] = ks[(d0 + i) * 129 + j];
            #pragma unroll
            for (int m = 0; m < 4; m++) vv[m] = vs[(e0 + m) * 129 + j];
            #pragma unroll
            for (int i = 0; i < 4; i++)
                #pragma unroll
                for (int m = 0; m < 4; m++) acc[i][m] += kd[i] * vv[m];
            if (e0 == 0) {
                #pragma unroll
                for (int i = 0; i < 4; i++) zacc[i] += kd[i];
            }
        }
    }
    int pc = chunk * 4 + jp;
    float* pp = g_ctx_part + ((size_t)pc * 64 + bh) * 1024;
    #pragma unroll
    for (int i = 0; i < 4; i++) {
        float4 v = make_float4(acc[i][0], acc[i][1], acc[i][2], acc[i][3]);
        *(float4*)(pp + (d0 + i) * 32 + e0) = v;
    }
    if (e0 == 0) {
        float* zp = g_z_part + ((size_t)pc * 64 + bh) * 32;
        #pragma unroll
        for (int i = 0; i < 4; i++) zp[d0 + i] = zacc[i];
    }
}

// ---------------------------------------------------------------------------
// K3b (stage B): reduce NPART partials, add memory tokens, fold SCALE / Z.
// ---------------------------------------------------------------------------
__global__ __launch_bounds__(1024) void k_ctx_reduce(const float* __restrict__ memkv) {
    __shared__ float zs[32];
    int bh = blockIdx.x;
    int b = bh >> 2, h = bh & 3;
    int tid = threadIdx.x;
    int d = tid >> 5, e = tid & 31;

    float acc = 0.f;
    #pragma unroll 8
    for (int c = 0; c < NPART; c++)
        acc += g_ctx_part[((size_t)c * 64 + bh) * 1024 + tid];

    float km = g_kmax[b * 128 + h * 32 + d];
    const float* mk = memkv + h * 128 + d * NMEM;
    const float* mv = memkv + 512 + h * 128 + e * NMEM;
    float zmem = 0.f;
    #pragma unroll
    for (int j = 0; j < NMEM; j++) {
        float ek = expf(mk[j] - km);
        acc += ek * mv[j];
        zmem += ek;
    }
    if (e == 0) {
        float z = zmem;
        #pragma unroll 8
        for (int c = 0; c < NPART; c++)
            z += g_z_part[((size_t)c * 64 + bh) * 32 + d];
        zs[d] = z;
    }
    __syncthreads();
    g_ctx[(size_t)bh * 1024 + tid] = acc * SCALE / zs[d];
}

// ---------------------------------------------------------------------------
// K4: fused epilogue, 64-col n-tile, register-lean for 2 CTAs/SM.
// ---------------------------------------------------------------------------
#define F_OSH  0
#define F_OSL  17408
#define F_WB0  34816
#define F_WB1  55296
#define F_CS   55296
#define FIN_SMEM 75776

__global__ __launch_bounds__(256, 2) void k_final_mma(const float* __restrict__ b_out,
                                                      const float* __restrict__ gout,
                                                      float* __restrict__ out) {
    extern __shared__ char smem[];
    uint32_t sb = smem_u32(smem);
    int tid = threadIdx.x;
    int lane = tid & 31, wid = tid >> 5;
    int wm = wid & 3, wn = wid >> 2;    // 4m x 2n warps; warp tile 64m x 32n
    int b = blockIdx.y;
    int n0 = blockIdx.x * 64;
    const float* qp = g_qkv + (size_t)b * QKVROWS * NDIM;

    auto w_stage = [&](int kc, int bufsel) {
        uint32_t dst = sb + F_WB0 + bufsel * 20480;
        #pragma unroll
        for (int t = 0; t < 4; t++) {
            int idx = tid + t * 256;          // 0..1023
            int r = idx >> 2, q = idx & 3;
            const __nv_bfloat16* src;
            uint32_t daddr;
            if (q < 2) {
                src = g_woh + r * HID + kc * 16 + q * 8;
                daddr = dst + r * 80 + q * 16;
            } else {
                src = g_wol + r * HID + kc * 16 + (q - 2) * 8;
                daddr = dst + r * 80 + 32 + (q - 2) * 16;
            }
            CP_ASYNC16(daddr, src);
        }
        CP_COMMIT();
    };
    w_stage(0, 0);

    float* cs = (float*)(smem + F_CS);
    #pragma unroll
    for (int t = 0; t < 4; t++) {
        int idx = tid + t * 256;
        *(float4*)(cs + idx * 4) = *(const float4*)(g_ctx + b * 4096 + idx * 4);
    }
    __syncthreads();

    {
        int h = tid >> 6, c = tid & 63;
        const float* colp = qp + (size_t)(h * 32) * NDIM + n0 + c;
        float qreg[32];
        float mx = -INFINITY;
        #pragma unroll
        for (int d = 0; d < 32; d++) { qreg[d] = colp[d * NDIM]; mx = fmaxf(mx, qreg[d]); }
        float s = 0.f;
        #pragma unroll
        for (int d = 0; d < 32; d++) { qreg[d] = expf(qreg[d] - mx); s += qreg[d]; }
        float inv = 1.f / s;
        #pragma unroll
        for (int d = 0; d < 32; d++) qreg[d] *= inv;
        const float* ch = cs + h * 1024;
        #pragma unroll
        for (int e = 0; e < 32; e += 2) {
            float a0 = 0.f, a1 = 0.f;
            #pragma unroll
            for (int d = 0; d < 32; d++) {
                a0 += ch[d * 32 + e]     * qreg[d];
                a1 += ch[d * 32 + e + 1] * qreg[d];
            }
            __nv_bfloat16 h0 = __float2bfloat16(a0);
            __nv_bfloat16 h1 = __float2bfloat16(a1);
            __nv_bfloat16 l0 = __float2bfloat16(a0 - __bfloat162float(h0));
            __nv_bfloat16 l1 = __float2bfloat16(a1 - __bfloat162float(h1));
            uint32_t hp = (uint32_t)*(uint16_t*)&h0 | ((uint32_t)*(uint16_t*)&h1 << 16);
            uint32_t lp = (uint32_t)*(uint16_t*)&l0 | ((uint32_t)*(uint16_t*)&l1 << 16);
            uint32_t off = (uint32_t)c * 272 + (h * 32 + e) * 2;
            *(uint32_t*)(smem + F_OSH + off) = hp;
            *(uint32_t*)(smem + F_OSL + off) = lp;
        }
    }
    __syncthreads();
    w_stage(1, 1);            // cs dead; overwrite union region

    float acc[4][4][4];
    #pragma unroll
    for (int i = 0; i < 4; i++)
        #pragma unroll
        for (int j = 0; j < 4; j++)
            #pragma unroll
            for (int r = 0; r < 4; r++) acc[i][j][r] = 0.f;

    for (int kc = 0; kc < 8; kc++) {
        if (kc < 7) { CP_WAIT(1); } else { CP_WAIT(0); }
        __syncthreads();
        uint32_t wbuf = sb + F_WB0 + (kc & 1) * 20480;

        uint32_t bh[4][2], bl[4][2];
        int l = lane & 15;
        uint32_t bko = (uint32_t)(kc * 32 + (l >> 3) * 16);
        #pragma unroll
        for (int ni = 0; ni < 4; ni++) {
            uint32_t rb = wn * 32 + ni * 8 + (l & 7);
            uint32_t boff = rb * 272 + bko;
            LDMATRIX_X2(bh[ni][0], bh[ni][1], sb + F_OSH + boff);
            LDMATRIX_X2(bl[ni][0], bl[ni][1], sb + F_OSL + boff);
        }
        uint32_t ako = (uint32_t)((lane >> 4) * 16);
        #pragma unroll
        for (int mi = 0; mi < 4; mi++) {
            uint32_t ra = wm * 64 + mi * 16 + (lane & 15);
            uint32_t ah[4], al[4];
            LDMATRIX_X4(ah[0], ah[1], ah[2], ah[3], wbuf + ra * 80 + ako);
            LDMATRIX_X4(al[0], al[1], al[2], al[3], wbuf + ra * 80 + 32 + ako);
            #pragma unroll
            for (int ni = 0; ni < 4; ni++) {
                MMA_BF16(acc[mi][ni][0], acc[mi][ni][1], acc[mi][ni][2], acc[mi][ni][3],
                         ah[0], ah[1], ah[2], ah[3], bh[ni][0], bh[ni][1]);
                MMA_BF16(acc[mi][ni][0], acc[mi][ni][1], acc[mi][ni][2], acc[mi][ni][3],
                         ah[0], ah[1], ah[2], ah[3], bl[ni][0], bl[ni][1]);
                MMA_BF16(acc[mi][ni][0], acc[mi][ni][1], acc[mi][ni][2], acc[mi][ni][3],
                         al[0], al[1], al[2], al[3], bh[ni][0], bh[ni][1]);
            }
        }
        __syncthreads();
        if (kc + 2 < 8) w_stage(kc + 2, kc & 1);
    }

    int tr = lane >> 2, tc2 = (lane & 3) * 2;
    float bo[4][2], go[4][2];
    #pragma unroll
    for (int mi = 0; mi < 4; mi++) {
        int o = wm * 64 + mi * 16 + tr;
        bo[mi][0] = b_out[o];  bo[mi][1] = b_out[o + 8];
        go[mi][0] = gout[o];   go[mi][1] = gout[o + 8];
    }
    float* red = (float*)(smem + F_OSH);
    float* colsc = (float*)(smem + F_OSL);
    int rp = wm * 8 + tr;
    #pragma unroll
    for (int ni = 0; ni < 4; ni++) {
        float s0 = 0.f, s1 = 0.f;
        #pragma unroll
        for (int mi = 0; mi < 4; mi++) {
            float v0 = acc[mi][ni][0] + bo[mi][0];
            float v1 = acc[mi][ni][1] + bo[mi][0];
            float v2 = acc[mi][ni][2] + bo[mi][1];
            float v3 = acc[mi][ni][3] + bo[mi][1];
            acc[mi][ni][0] = v0; acc[mi][ni][1] = v1;
            acc[mi][ni][2] = v2; acc[mi][ni][3] = v3;
            s0 += v0 * v0 + v2 * v2;
            s1 += v1 * v1 + v3 * v3;
        }
        int col = wn * 32 + ni * 8 + tc2;
        red[col * 32 + rp]       = s0;
        red[(col + 1) * 32 + rp] = s1;
    }
    __syncthreads();
    if (tid < 64) {
        float s = 0.f;
        #pragma unroll 8
        for (int t = 0; t < 32; t++) s += red[tid * 32 + t];
        colsc[tid] = 16.0f / fmaxf(sqrtf(s), EPSN);
    }
    __syncthreads();

    float* ob = out + (size_t)b * CDIM * NDIM;
    #pragma unroll
    for (int mi = 0; mi < 4; mi++) {
        int o0 = wm * 64 + mi * 16 + tr;
        #pragma unroll
        for (int ni = 0; ni < 4; ni++) {
            int col = wn * 32 + ni * 8 + tc2;
            float sc0 = colsc[col], sc1 = colsc[col + 1];
            float2 v0 = make_float2(acc[mi][ni][0] * sc0 * go[mi][0],
                                    acc[mi][ni][1] * sc1 * go[mi][0]);
            float2 v1 = make_float2(acc[mi][ni][2] * sc0 * go[mi][1],
                                    acc[mi][ni][3] * sc1 * go[mi][1]);
            *(float2*)(ob + (size_t)o0 * NDIM + n0 + col)       = v0;
            *(float2*)(ob + (size_t)(o0 + 8) * NDIM + n0 + col) = v1;
        }
    }
}

// ---------------------------------------------------------------------------
extern "C" void kernel_launch(void* const* d_in, const int* in_sizes, int n_in,
                              void* d_out, int out_size) {
    const float* x      = (const float*)d_in[0];
    const float* norm_g = (const float*)d_in[1];
    const float* w_qkv  = (const float*)d_in[2];
    const float* mem_kv = (const float*)d_in[3];
    const float* w_out  = (const float*)d_in[4];
    const float* b_out  = (const float*)d_in[5];
    const float* out_g  = (const float*)d_in[6];
    float* out = (float*)d_out;

    // One-time host-side setup (no device allocation; identical enqueued
    // work on every call).
    static cudaStream_t s1 = nullptr;
    static cudaEvent_t evFork = nullptr, evJoin = nullptr;
    if (s1 == nullptr) {
        cudaStreamCreateWithFlags(&s1, cudaStreamNonBlocking);
        cudaEventCreateWithFlags(&evFork, cudaEventDisableTiming);
        cudaEventCreateWithFlags(&evJoin, cudaEventDisableTiming);
    }

    k_kinit<<<(BATCH * 128) / 256, 256>>>(mem_kv);
    k_wsplit<<<(QKVROWS * CDIM) / 256, 256>>>(w_qkv, norm_g);
    k_osplit<<<(CDIM * HID) / 256, 256>>>(w_out);

    cudaFuncSetAttribute(k_xprep, cudaFuncAttributeMaxDynamicSharedMemorySize, XP_SMEM);
    dim3 gx(NDIM / XP_NT, BATCH);
    k_xprep<<<gx, 256, XP_SMEM>>>(x);

    cudaFuncSetAttribute(k_qkv_mma, cudaFuncAttributeMaxDynamicSharedMemorySize, 2 * STG);
    // KV m-tiles first (ctx chain depends on them)
    dim3 gkv(2, NDIM / 128, BATCH);
    k_qkv_mma<<<gkv, 256, 2 * STG>>>(128, 1);

    // Fork: Q m-tile GEMM on s1, concurrent with the ctx chain on stream 0.
    cudaEventRecord(evFork, 0);
    cudaStreamWaitEvent(s1, evFork, 0);
    dim3 gq(1, NDIM / 128, BATCH);
    k_qkv_mma<<<gq, 256, 2 * STG, s1>>>(0, 0);
    cudaEventRecord(evJoin, s1);

    dim3 g3(NCHUNK, 64);
    k_ctx_part<<<g3, 256>>>();
    k_ctx_reduce<<<BATCH * HEADS, 1024>>>(mem_kv);

    // Join: k_final needs both Q (s1) and ctx (stream 0).
    cudaStreamWaitEvent(0, evJoin, 0);

    cudaFuncSetAttribute(k_final_mma, cudaFuncAttributeMaxDynamicSharedMemorySize, FIN_SMEM);
    dim3 g4(NDIM / 64, BATCH);
    k_final_mma<<<g4, 256, FIN_SMEM>>>(b_out, out_g, out);
}

// round 15
// speedup vs baseline: 1.5297x; 1.5297x over previous
#include <cuda_runtime.h>
#include <cuda_bf16.h>
#include <math.h>
#include <stdint.h>

// Problem constants
#define BATCH 16
#define CDIM 256
#define NDIM 4096          // 64*64 spatial
#define HEADS 4
#define ADIM 32
#define HID 128
#define QKVROWS 384        // 3*HID
#define NMEM 4
#define SCALE 0.17677669529663687f   // 32^-0.5
#define EPSN 1e-12f
#define NCHUNK 16          // ctx n-chunks
#define NPART  64          // NCHUNK*4 partials

// Scratch (device globals: allocation-free per harness rules)
__device__ float g_qkv[(size_t)BATCH * QKVROWS * NDIM]; // ~100MB
__device__ float g_kmax[BATCH * HEADS * ADIM];
__device__ float g_ctx[BATCH * HEADS * ADIM * ADIM];    // already * SCALE / Z
__device__ float g_ctx_part[(size_t)NPART * 64 * 1024]; // 16MB partials
__device__ float g_z_part[NPART * 64 * 32];
// Pre-split bf16 operands (k-contiguous rows)
__device__ __nv_bfloat16 g_wh[QKVROWS * CDIM];
__device__ __nv_bfloat16 g_wl[QKVROWS * CDIM];
__device__ __nv_bfloat16 g_xh[(size_t)BATCH * NDIM * CDIM];  // [b][n][c]
__device__ __nv_bfloat16 g_xl[(size_t)BATCH * NDIM * CDIM];
// Pre-split w_out (256 x 128)
__device__ __nv_bfloat16 g_woh[CDIM * HID];
__device__ __nv_bfloat16 g_wol[CDIM * HID];

// ---------------------------------------------------------------------------
__device__ __forceinline__ uint32_t smem_u32(const void* p) {
    uint32_t a;
    asm("{ .reg .u64 t; cvta.to.shared.u64 t, %1; cvt.u32.u64 %0, t; }" : "=r"(a) : "l"(p));
    return a;
}
#define CP_ASYNC16(saddr, gaddr) \
    asm volatile("cp.async.cg.shared.global [%0], [%1], 16;" :: "r"(saddr), "l"(gaddr) : "memory")
#define CP_COMMIT() asm volatile("cp.async.commit_group;" ::: "memory")
#define CP_WAIT(n)  asm volatile("cp.async.wait_group %0;" :: "n"(n) : "memory")

#define LDMATRIX_X4(r0, r1, r2, r3, addr) \
    asm volatile("ldmatrix.sync.aligned.m8n8.x4.shared.b16 {%0,%1,%2,%3}, [%4];" \
                 : "=r"(r0), "=r"(r1), "=r"(r2), "=r"(r3) : "r"(addr))
#define LDMATRIX_X2(r0, r1, addr) \
    asm volatile("ldmatrix.sync.aligned.m8n8.x2.shared.b16 {%0,%1}, [%2];" \
                 : "=r"(r0), "=r"(r1) : "r"(addr))
#define MMA_BF16(d0, d1, d2, d3, a0, a1, a2, a3, b0, b1) \
    asm volatile("mma.sync.aligned.m16n8k16.row.col.f32.bf16.bf16.f32 " \
                 "{%0,%1,%2,%3}, {%4,%5,%6,%7}, {%8,%9}, {%0,%1,%2,%3};" \
                 : "+f"(d0), "+f"(d1), "+f"(d2), "+f"(d3) \
                 : "r"(a0), "r"(a1), "r"(a2), "r"(a3), "r"(b0), "r"(b1))

// Deterministic float atomic max (int/uint ordering trick)
__device__ __forceinline__ void atomicMaxF(float* addr, float v) {
    if (v >= 0.f) atomicMax((int*)addr, __float_as_int(v));
    else          atomicMin((unsigned int*)addr, __float_as_uint(v));
}

// ---------------------------------------------------------------------------
// K0: merged prep — wsplit (blocks 0..383), osplit (384..511), kinit (512..519)
// ---------------------------------------------------------------------------
__global__ __launch_bounds__(256) void k_prep(const float* __restrict__ wqkv,
                                              const float* __restrict__ gch,
                                              const float* __restrict__ wout,
                                              const float* __restrict__ memkv) {
    int blk = blockIdx.x;
    int tid = threadIdx.x;
    if (blk < 384) {
        int e = blk * 256 + tid;
        int k = e & 255;
        float w = wqkv[e] * gch[k];
        __nv_bfloat16 hi = __float2bfloat16(w);
        __nv_bfloat16 lo = __float2bfloat16(w - __bfloat162float(hi));
        g_wh[e] = hi;
        g_wl[e] = lo;
    } else if (blk < 512) {
        int e = (blk - 384) * 256 + tid;
        float w = wout[e];
        __nv_bfloat16 hi = __float2bfloat16(w);
        __nv_bfloat16 lo = __float2bfloat16(w - __bfloat162float(hi));
        g_woh[e] = hi;
        g_wol[e] = lo;
    } else {
        int idx = (blk - 512) * 256 + tid;    // b*128 + hd
        int hd = idx & 127;
        float mm = -INFINITY;
        #pragma unroll
        for (int j = 0; j < NMEM; j++) mm = fmaxf(mm, memkv[hd * NMEM + j]);
        g_kmax[idx] = mm;
    }
}

// ---------------------------------------------------------------------------
// K1: fused rnorm + transpose + bf16 split.  32-n tile: 34.9KB smem -> 6 CTAs/SM.
// ---------------------------------------------------------------------------
#define XP_NT  32
#define XP_PAD 33
#define XP_SMEM ((256 * XP_PAD + 8 * XP_NT + XP_NT) * 4)

__global__ __launch_bounds__(256) void k_xprep(const float* __restrict__ x) {
    extern __shared__ float xs[];
    float* red = xs + 256 * XP_PAD;   // [8][32]
    float* rns = red + 8 * XP_NT;     // [32]
    int n0 = blockIdx.x * XP_NT;
    int b  = blockIdx.y;
    int tid = threadIdx.x;
    const float* xb = x + (size_t)b * CDIM * NDIM + n0;

    #pragma unroll
    for (int t = 0; t < 8; t++) {
        int idx = tid + t * 256;
        int c = idx >> 3, nch = idx & 7;
        float4 v = *(const float4*)(xb + (size_t)c * NDIM + nch * 4);
        float* row = xs + c * XP_PAD + nch * 4;
        row[0] = v.x; row[1] = v.y; row[2] = v.z; row[3] = v.w;
    }
    __syncthreads();

    {
        int n = tid & 31, p = tid >> 5;
        const float* col = xs + (p * 32) * XP_PAD + n;
        float s = 0.f;
        #pragma unroll 8
        for (int i = 0; i < 32; i++) {
            float v = col[i * XP_PAD];
            s += v * v;
        }
        red[p * XP_NT + n] = s;
    }
    __syncthreads();
    if (tid < XP_NT) {
        float s = 0.f;
        #pragma unroll
        for (int p = 0; p < 8; p++) s += red[p * XP_NT + tid];
        rns[tid] = 16.0f / fmaxf(sqrtf(s), EPSN);
    }
    __syncthreads();

    #pragma unroll
    for (int t = 0; t < 16; t++) {
        int job = tid + t * 256;
        int cp = job & 127, n = job >> 7;
        float rn = rns[n];
        float v0 = xs[(2 * cp + 0) * XP_PAD + n] * rn;
        float v1 = xs[(2 * cp + 1) * XP_PAD + n] * rn;
        __nv_bfloat16 h0 = __float2bfloat16(v0);
        __nv_bfloat16 h1 = __float2bfloat16(v1);
        __nv_bfloat16 l0 = __float2bfloat16(v0 - __bfloat162float(h0));
        __nv_bfloat16 l1 = __float2bfloat16(v1 - __bfloat162float(h1));
        uint32_t hp = (uint32_t)*(uint16_t*)&h0 | ((uint32_t)*(uint16_t*)&h1 << 16);
        uint32_t lp = (uint32_t)*(uint16_t*)&l0 | ((uint32_t)*(uint16_t*)&l1 << 16);
        size_t o = ((size_t)b * NDIM + n0 + n) * CDIM + cp * 2;
        *(uint32_t*)&g_xh[o] = hp;
        *(uint32_t*)&g_xl[o] = lp;
    }
}

// ---------------------------------------------------------------------------
// K2: QKV GEMM via mma.sync bf16 (split-bf16, 3 terms).
// Epilogue atomicMax's K rows into g_kmax (blockIdx.x == 1).
// ---------------------------------------------------------------------------
#define RS 80
#define T_AH 0
#define T_AL 10240
#define T_BH 20480
#define T_BL 30720
#define STG  40960

__global__ __launch_bounds__(256) void k_qkv_mma() {
    extern __shared__ char smem[];
    uint32_t sb = smem_u32(smem);
    int tid = threadIdx.x;
    int lane = tid & 31, wid = tid >> 5;
    int wm = wid & 1, wn = wid >> 1;
    int m0 = blockIdx.x * 128;
    int n0 = blockIdx.y * 128;
    int b  = blockIdx.z;

    const __nv_bfloat16* xhb = g_xh + (size_t)b * NDIM * CDIM;
    const __nv_bfloat16* xlb = g_xl + (size_t)b * NDIM * CDIM;

    float acc[4][4][4];
    #pragma unroll
    for (int i = 0; i < 4; i++)
        #pragma unroll
        for (int j = 0; j < 4; j++)
            #pragma unroll
            for (int r = 0; r < 4; r++) acc[i][j][r] = 0.f;

    auto issue_stage = [&](int s) {
        int k0 = s * 32;
        uint32_t dst_base = sb + (s & 1) * STG;
        #pragma unroll
        for (int t = 0; t < 8; t++) {
            int idx = tid + t * 256;
            int tile = idx >> 9;
            int i = idx & 511;
            int row = i >> 2, pos = i & 3;
            uint32_t daddr = dst_base + tile * 10240 + row * RS + pos * 16;
            const __nv_bfloat16* src;
            if (tile == 0)      src = g_wh + (size_t)(m0 + row) * CDIM + k0 + pos * 8;
            else if (tile == 1) src = g_wl + (size_t)(m0 + row) * CDIM + k0 + pos * 8;
            else if (tile == 2) src = xhb + (size_t)(n0 + row) * CDIM + k0 + pos * 8;
            else                src = xlb + (size_t)(n0 + row) * CDIM + k0 + pos * 8;
            CP_ASYNC16(daddr, src);
        }
        CP_COMMIT();
    };

    issue_stage(0);
    for (int s = 0; s < 8; s++) {
        if (s + 1 < 8) {
            issue_stage(s + 1);
            CP_WAIT(1);
        } else {
            CP_WAIT(0);
        }
        __syncthreads();
        uint32_t buf = sb + (s & 1) * STG;

        #pragma unroll
        for (int ks = 0; ks < 2; ks++) {
            uint32_t ah[4][4], al[4][4], bh[4][2], bl[4][2];
            int akoff = (ks * 16 + (lane >> 4) * 8) * 2;
            int arow = (lane & 15);
            #pragma unroll
            for (int mi = 0; mi < 4; mi++) {
                int rb = wm * 64 + mi * 16 + arow;
                LDMATRIX_X4(ah[mi][0], ah[mi][1], ah[mi][2], ah[mi][3], buf + T_AH + rb * RS + akoff);
                LDMATRIX_X4(al[mi][0], al[mi][1], al[mi][2], al[mi][3], buf + T_AL + rb * RS + akoff);
            }
            int l = lane & 15;
            int bkoff = (ks * 16 + (l >> 3) * 8) * 2;
            int brow = l & 7;
            #pragma unroll
            for (int ni = 0; ni < 4; ni++) {
                int rb = wn * 32 + ni * 8 + brow;
                LDMATRIX_X2(bh[ni][0], bh[ni][1], buf + T_BH + rb * RS + bkoff);
                LDMATRIX_X2(bl[ni][0], bl[ni][1], buf + T_BL + rb * RS + bkoff);
            }
            #pragma unroll
            for (int mi = 0; mi < 4; mi++)
                #pragma unroll
                for (int ni = 0; ni < 4; ni++)
                    MMA_BF16(acc[mi][ni][0], acc[mi][ni][1], acc[mi][ni][2], acc[mi][ni][3],
                             ah[mi][0], ah[mi][1], ah[mi][2], ah[mi][3], bh[ni][0], bh[ni][1]);
            #pragma unroll
            for (int mi = 0; mi < 4; mi++)
                #pragma unroll
                for (int ni = 0; ni < 4; ni++)
                    MMA_BF16(acc[mi][ni][0], acc[mi][ni][1], acc[mi][ni][2], acc[mi][ni][3],
                             ah[mi][0], ah[mi][1], ah[mi][2], ah[mi][3], bl[ni][0], bl[ni][1]);
            #pragma unroll
            for (int mi = 0; mi < 4; mi++)
                #pragma unroll
                for (int ni = 0; ni < 4; ni++)
                    MMA_BF16(acc[mi][ni][0], acc[mi][ni][1], acc[mi][ni][2], acc[mi][ni][3],
                             al[mi][0], al[mi][1], al[mi][2], al[mi][3], bh[ni][0], bh[ni][1]);
        }
        __syncthreads();
    }

    float* outp = g_qkv + (size_t)b * QKVROWS * NDIM;
    int tr = lane >> 2, tc = (lane & 3) * 2;
    #pragma unroll
    for (int mi = 0; mi < 4; mi++) {
        #pragma unroll
        for (int ni = 0; ni < 4; ni++) {
            int o0 = m0 + wm * 64 + mi * 16 + tr;
            int nn = n0 + wn * 32 + ni * 8 + tc;
            float2 v0 = make_float2(acc[mi][ni][0], acc[mi][ni][1]);
            float2 v1 = make_float2(acc[mi][ni][2], acc[mi][ni][3]);
            *(float2*)(outp + (size_t)o0 * NDIM + nn)       = v0;
            *(float2*)(outp + (size_t)(o0 + 8) * NDIM + nn) = v1;
        }
    }

    if (blockIdx.x == 1) {
        #pragma unroll
        for (int mi = 0; mi < 4; mi++) {
            float mA = -INFINITY, mB = -INFINITY;
            #pragma unroll
            for (int ni = 0; ni < 4; ni++) {
                mA = fmaxf(mA, fmaxf(acc[mi][ni][0], acc[mi][ni][1]));
                mB = fmaxf(mB, fmaxf(acc[mi][ni][2], acc[mi][ni][3]));
            }
            mA = fmaxf(mA, __shfl_xor_sync(0xffffffffu, mA, 1));
            mA = fmaxf(mA, __shfl_xor_sync(0xffffffffu, mA, 2));
            mB = fmaxf(mB, __shfl_xor_sync(0xffffffffu, mB, 1));
            mB = fmaxf(mB, __shfl_xor_sync(0xffffffffu, mB, 2));
            if ((lane & 3) == 0) {
                int hd = wm * 64 + mi * 16 + tr;
                atomicMaxF(&g_kmax[b * 128 + hd], mA);
                atomicMaxF(&g_kmax[b * 128 + hd + 8], mB);
            }
        }
    }
}

// ---------------------------------------------------------------------------
// K3b (stage A): partial ctx over an n-chunk of 256, split 4-way in j.
// ---------------------------------------------------------------------------
__global__ __launch_bounds__(256) void k_ctx_part() {
    __shared__ float ks[32 * 129];
    __shared__ float vs[32 * 129];
    __shared__ float kml[32];
    int chunk = blockIdx.x;
    int bh = blockIdx.y;
    int b = bh >> 2, h = bh & 3;
    int tid = threadIdx.x;
    int jp = tid >> 6;
    int tile = tid & 63;
    int d0 = (tile & 7) * 4;
    int e0 = (tile >> 3) * 4;

    const float* base = g_qkv + (size_t)b * QKVROWS * NDIM;
    const float* kp = base + (size_t)(HID + h * ADIM) * NDIM;
    const float* vp = base + (size_t)(2 * HID + h * ADIM) * NDIM;

    if (tid < 32) kml[tid] = g_kmax[b * 128 + h * 32 + tid];
    __syncthreads();

    float acc[4][4];
    #pragma unroll
    for (int i = 0; i < 4; i++)
        #pragma unroll
        for (int m = 0; m < 4; m++) acc[i][m] = 0.f;
    float zacc[4] = {0.f, 0.f, 0.f, 0.f};

    for (int st = 0; st < 2; st++) {
        int n0 = chunk * 256 + st * 128;
        __syncthreads();
        #pragma unroll
        for (int f = tid; f < 1024; f += 256) {
            int r = f >> 5, c4 = (f & 31) * 4;
            float km = kml[r];
            float4 kv = *(const float4*)(kp + (size_t)r * NDIM + n0 + c4);
            ks[r * 129 + c4 + 0] = expf(kv.x - km);
            ks[r * 129 + c4 + 1] = expf(kv.y - km);
            ks[r * 129 + c4 + 2] = expf(kv.z - km);
            ks[r * 129 + c4 + 3] = expf(kv.w - km);
            float4 vv = *(const float4*)(vp + (size_t)r * NDIM + n0 + c4);
            vs[r * 129 + c4 + 0] = vv.x;
            vs[r * 129 + c4 + 1] = vv.y;
            vs[r * 129 + c4 + 2] = vv.z;
            vs[r * 129 + c4 + 3] = vv.w;
        }
        __syncthreads();
        #pragma unroll 4
        for (int jj = 0; jj < 32; jj++) {
            int j = jp * 32 + jj;
            float kd[4], vv[4];
            #pragma unroll
            for (int i = 0; i < 4; i++) kd[i] = ks[(d0 + i) * 129 + j];
            #pragma unroll
            for (int m = 0; m < 4; m++) vv[m] = vs[(e0 + m) * 129 + j];
            #pragma unroll
            for (int i = 0; i < 4; i++)
                #pragma unroll
                for (int m = 0; m < 4; m++) acc[i][m] += kd[i] * vv[m];
            if (e0 == 0) {
                #pragma unroll
                for (int i = 0; i < 4; i++) zacc[i] += kd[i];
            }
        }
    }
    int pc = chunk * 4 + jp;
    float* pp = g_ctx_part + ((size_t)pc * 64 + bh) * 1024;
    #pragma unroll
    for (int i = 0; i < 4; i++) {
        float4 v = make_float4(acc[i][0], acc[i][1], acc[i][2], acc[i][3]);
        *(float4*)(pp + (d0 + i) * 32 + e0) = v;
    }
    if (e0 == 0) {
        float* zp = g_z_part + ((size_t)pc * 64 + bh) * 32;
        #pragma unroll
        for (int i = 0; i < 4; i++) zp[d0 + i] = zacc[i];
    }
}

// ---------------------------------------------------------------------------
// K3b (stage B): reduce NPART partials, add memory tokens, fold SCALE / Z.
// ---------------------------------------------------------------------------
__global__ __launch_bounds__(1024) void k_ctx_reduce(const float* __restrict__ memkv) {
    __shared__ float zs[32];
    int bh = blockIdx.x;
    int b = bh >> 2, h = bh & 3;
    int tid = threadIdx.x;
    int d = tid >> 5, e = tid & 31;

    float acc = 0.f;
    #pragma unroll 8
    for (int c = 0; c < NPART; c++)
        acc += g_ctx_part[((size_t)c * 64 + bh) * 1024 + tid];

    float km = g_kmax[b * 128 + h * 32 + d];
    const float* mk = memkv + h * 128 + d * NMEM;
    const float* mv = memkv + 512 + h * 128 + e * NMEM;
    float zmem = 0.f;
    #pragma unroll
    for (int j = 0; j < NMEM; j++) {
        float ek = expf(mk[j] - km);
        acc += ek * mv[j];
        zmem += ek;
    }
    if (e == 0) {
        float z = zmem;
        #pragma unroll 8
        for (int c = 0; c < NPART; c++)
            z += g_z_part[((size_t)c * 64 + bh) * 32 + d];
        zs[d] = z;
    }
    __syncthreads();
    g_ctx[(size_t)bh * 1024 + tid] = acc * SCALE / zs[d];
}

// ---------------------------------------------------------------------------
// K4: fused epilogue, 64-col n-tile, register-lean for 2 CTAs/SM.
// ---------------------------------------------------------------------------
#define F_OSH  0
#define F_OSL  17408
#define F_WB0  34816
#define F_WB1  55296
#define F_CS   55296
#define FIN_SMEM 75776

__global__ __launch_bounds__(256, 2) void k_final_mma(const float* __restrict__ b_out,
                                                      const float* __restrict__ gout,
                                                      float* __restrict__ out) {
    extern __shared__ char smem[];
    uint32_t sb = smem_u32(smem);
    int tid = threadIdx.x;
    int lane = tid & 31, wid = tid >> 5;
    int wm = wid & 3, wn = wid >> 2;    // 4m x 2n warps; warp tile 64m x 32n
    int b = blockIdx.y;
    int n0 = blockIdx.x * 64;
    const float* qp = g_qkv + (size_t)b * QKVROWS * NDIM;

    auto w_stage = [&](int kc, int bufsel) {
        uint32_t dst = sb + F_WB0 + bufsel * 20480;
        #pragma unroll
        for (int t = 0; t < 4; t++) {
            int idx = tid + t * 256;          // 0..1023
            int r = idx >> 2, q = idx & 3;
            const __nv_bfloat16* src;
            uint32_t daddr;
            if (q < 2) {
                src = g_woh + r * HID + kc * 16 + q * 8;
                daddr = dst + r * 80 + q * 16;
            } else {
                src = g_wol + r * HID + kc * 16 + (q - 2) * 8;
                daddr = dst + r * 80 + 32 + (q - 2) * 16;
            }
            CP_ASYNC16(daddr, src);
        }
        CP_COMMIT();
    };
    w_stage(0, 0);

    float* cs = (float*)(smem + F_CS);
    #pragma unroll
    for (int t = 0; t < 4; t++) {
        int idx = tid + t * 256;
        *(float4*)(cs + idx * 4) = *(const float4*)(g_ctx + b * 4096 + idx * 4);
    }
    __syncthreads();

    {
        int h = tid >> 6, c = tid & 63;
        const float* colp = qp + (size_t)(h * 32) * NDIM + n0 + c;
        float qreg[32];
        float mx = -INFINITY;
        #pragma unroll
        for (int d = 0; d < 32; d++) { qreg[d] = colp[d * NDIM]; mx = fmaxf(mx, qreg[d]); }
        float s = 0.f;
        #pragma unroll
        for (int d = 0; d < 32; d++) { qreg[d] = expf(qreg[d] - mx); s += qreg[d]; }
        float inv = 1.f / s;
        #pragma unroll
        for (int d = 0; d < 32; d++) qreg[d] *= inv;
        const float* ch = cs + h * 1024;
        #pragma unroll
        for (int e = 0; e < 32; e += 2) {
            float a0 = 0.f, a1 = 0.f;
            #pragma unroll
            for (int d = 0; d < 32; d++) {
                a0 += ch[d * 32 + e]     * qreg[d];
                a1 += ch[d * 32 + e + 1] * qreg[d];
            }
            __nv_bfloat16 h0 = __float2bfloat16(a0);
            __nv_bfloat16 h1 = __float2bfloat16(a1);
            __nv_bfloat16 l0 = __float2bfloat16(a0 - __bfloat162float(h0));
            __nv_bfloat16 l1 = __float2bfloat16(a1 - __bfloat162float(h1));
            uint32_t hp = (uint32_t)*(uint16_t*)&h0 | ((uint32_t)*(uint16_t*)&h1 << 16);
            uint32_t lp = (uint32_t)*(uint16_t*)&l0 | ((uint32_t)*(uint16_t*)&l1 << 16);
            uint32_t off = (uint32_t)c * 272 + (h * 32 + e) * 2;
            *(uint32_t*)(smem + F_OSH + off) = hp;
            *(uint32_t*)(smem + F_OSL + off) = lp;
        }
    }
    __syncthreads();
    w_stage(1, 1);            // cs dead; overwrite union region

    float acc[4][4][4];
    #pragma unroll
    for (int i = 0; i < 4; i++)
        #pragma unroll
        for (int j = 0; j < 4; j++)
            #pragma unroll
            for (int r = 0; r < 4; r++) acc[i][j][r] = 0.f;

    for (int kc = 0; kc < 8; kc++) {
        if (kc < 7) { CP_WAIT(1); } else { CP_WAIT(0); }
        __syncthreads();
        uint32_t wbuf = sb + F_WB0 + (kc & 1) * 20480;

        uint32_t bh[4][2], bl[4][2];
        int l = lane & 15;
        uint32_t bko = (uint32_t)(kc * 32 + (l >> 3) * 16);
        #pragma unroll
        for (int ni = 0; ni < 4; ni++) {
            uint32_t rb = wn * 32 + ni * 8 + (l & 7);
            uint32_t boff = rb * 272 + bko;
            LDMATRIX_X2(bh[ni][0], bh[ni][1], sb + F_OSH + boff);
            LDMATRIX_X2(bl[ni][0], bl[ni][1], sb + F_OSL + boff);
        }
        uint32_t ako = (uint32_t)((lane >> 4) * 16);
        #pragma unroll
        for (int mi = 0; mi < 4; mi++) {
            uint32_t ra = wm * 64 + mi * 16 + (lane & 15);
            uint32_t ah[4], al[4];
            LDMATRIX_X4(ah[0], ah[1], ah[2], ah[3], wbuf + ra * 80 + ako);
            LDMATRIX_X4(al[0], al[1], al[2], al[3], wbuf + ra * 80 + 32 + ako);
            #pragma unroll
            for (int ni = 0; ni < 4; ni++) {
                MMA_BF16(acc[mi][ni][0], acc[mi][ni][1], acc[mi][ni][2], acc[mi][ni][3],
                         ah[0], ah[1], ah[2], ah[3], bh[ni][0], bh[ni][1]);
                MMA_BF16(acc[mi][ni][0], acc[mi][ni][1], acc[mi][ni][2], acc[mi][ni][3],
                         ah[0], ah[1], ah[2], ah[3], bl[ni][0], bl[ni][1]);
                MMA_BF16(acc[mi][ni][0], acc[mi][ni][1], acc[mi][ni][2], acc[mi][ni][3],
                         al[0], al[1], al[2], al[3], bh[ni][0], bh[ni][1]);
            }
        }
        __syncthreads();
        if (kc + 2 < 8) w_stage(kc + 2, kc & 1);
    }

    int tr = lane >> 2, tc2 = (lane & 3) * 2;
    float bo[4][2], go[4][2];
    #pragma unroll
    for (int mi = 0; mi < 4; mi++) {
        int o = wm * 64 + mi * 16 + tr;
        bo[mi][0] = b_out[o];  bo[mi][1] = b_out[o + 8];
        go[mi][0] = gout[o];   go[mi][1] = gout[o + 8];
    }
    float* red = (float*)(smem + F_OSH);
    float* colsc = (float*)(smem + F_OSL);
    int rp = wm * 8 + tr;
    #pragma unroll
    for (int ni = 0; ni < 4; ni++) {
        float s0 = 0.f, s1 = 0.f;
        #pragma unroll
        for (int mi = 0; mi < 4; mi++) {
            float v0 = acc[mi][ni][0] + bo[mi][0];
            float v1 = acc[mi][ni][1] + bo[mi][0];
            float v2 = acc[mi][ni][2] + bo[mi][1];
            float v3 = acc[mi][ni][3] + bo[mi][1];
            acc[mi][ni][0] = v0; acc[mi][ni][1] = v1;
            acc[mi][ni][2] = v2; acc[mi][ni][3] = v3;
            s0 += v0 * v0 + v2 * v2;
            s1 += v1 * v1 + v3 * v3;
        }
        int col = wn * 32 + ni * 8 + tc2;
        red[col * 32 + rp]       = s0;
        red[(col + 1) * 32 + rp] = s1;
    }
    __syncthreads();
    if (tid < 64) {
        float s = 0.f;
        #pragma unroll 8
        for (int t = 0; t < 32; t++) s += red[tid * 32 + t];
        colsc[tid] = 16.0f / fmaxf(sqrtf(s), EPSN);
    }
    __syncthreads();

    float* ob = out + (size_t)b * CDIM * NDIM;
    #pragma unroll
    for (int mi = 0; mi < 4; mi++) {
        int o0 = wm * 64 + mi * 16 + tr;
        #pragma unroll
        for (int ni = 0; ni < 4; ni++) {
            int col = wn * 32 + ni * 8 + tc2;
            float sc0 = colsc[col], sc1 = colsc[col + 1];
            float2 v0 = make_float2(acc[mi][ni][0] * sc0 * go[mi][0],
                                    acc[mi][ni][1] * sc1 * go[mi][0]);
            float2 v1 = make_float2(acc[mi][ni][2] * sc0 * go[mi][1],
                                    acc[mi][ni][3] * sc1 * go[mi][1]);
            *(float2*)(ob + (size_t)o0 * NDIM + n0 + col)       = v0;
            *(float2*)(ob + (size_t)(o0 + 8) * NDIM + n0 + col) = v1;
        }
    }
}

// ---------------------------------------------------------------------------
extern "C" void kernel_launch(void* const* d_in, const int* in_sizes, int n_in,
                              void* d_out, int out_size) {
    const float* x      = (const float*)d_in[0];
    const float* norm_g = (const float*)d_in[1];
    const float* w_qkv  = (const float*)d_in[2];
    const float* mem_kv = (const float*)d_in[3];
    const float* w_out  = (const float*)d_in[4];
    const float* b_out  = (const float*)d_in[5];
    const float* out_g  = (const float*)d_in[6];
    float* out = (float*)d_out;

    k_prep<<<520, 256>>>(w_qkv, norm_g, w_out, mem_kv);

    cudaFuncSetAttribute(k_xprep, cudaFuncAttributeMaxDynamicSharedMemorySize, XP_SMEM);
    dim3 gx(NDIM / XP_NT, BATCH);
    k_xprep<<<gx, 256, XP_SMEM>>>(x);

    cudaFuncSetAttribute(k_qkv_mma, cudaFuncAttributeMaxDynamicSharedMemorySize, 2 * STG);
    dim3 g2(QKVROWS / 128, NDIM / 128, BATCH);
    k_qkv_mma<<<g2, 256, 2 * STG>>>();

    dim3 g3(NCHUNK, 64);
    k_ctx_part<<<g3, 256>>>();
    k_ctx_reduce<<<BATCH * HEADS, 1024>>>(mem_kv);

    cudaFuncSetAttribute(k_final_mma, cudaFuncAttributeMaxDynamicSharedMemorySize, FIN_SMEM);
    dim3 g4(NDIM / 64, BATCH);
    k_final_mma<<<g4, 256, FIN_SMEM>>>(b_out, out_g, out);
}

// round 16
// speedup vs baseline: 1.5410x; 1.0074x over previous
#include <cuda_runtime.h>
#include <cuda_bf16.h>
#include <math.h>
#include <stdint.h>

// Problem constants
#define BATCH 16
#define CDIM 256
#define NDIM 4096          // 64*64 spatial
#define HEADS 4
#define ADIM 32
#define HID 128
#define QKVROWS 384        // 3*HID
#define NMEM 4
#define SCALE 0.17677669529663687f   // 32^-0.5
#define EPSN 1e-12f
#define NCHUNK 16          // ctx n-chunks
#define NPART  64          // NCHUNK*4 partials

// Scratch (device globals: allocation-free per harness rules)
__device__ float g_qkv[(size_t)BATCH * QKVROWS * NDIM]; // ~100MB
__device__ float g_kmax[BATCH * HEADS * ADIM];
__device__ float g_ctx[BATCH * HEADS * ADIM * ADIM];    // already * SCALE / Z
__device__ float g_ctx_part[(size_t)NPART * 64 * 1024]; // 16MB partials
__device__ float g_z_part[NPART * 64 * 32];
// Pre-split bf16 operands (k-contiguous rows)
__device__ __nv_bfloat16 g_wh[QKVROWS * CDIM];
__device__ __nv_bfloat16 g_wl[QKVROWS * CDIM];
__device__ __nv_bfloat16 g_xh[(size_t)BATCH * NDIM * CDIM];  // [b][n][c]
__device__ __nv_bfloat16 g_xl[(size_t)BATCH * NDIM * CDIM];
// Pre-split w_out (256 x 128)
__device__ __nv_bfloat16 g_woh[CDIM * HID];
__device__ __nv_bfloat16 g_wol[CDIM * HID];

// ---------------------------------------------------------------------------
__device__ __forceinline__ uint32_t smem_u32(const void* p) {
    uint32_t a;
    asm("{ .reg .u64 t; cvta.to.shared.u64 t, %1; cvt.u32.u64 %0, t; }" : "=r"(a) : "l"(p));
    return a;
}
#define CP_ASYNC16(saddr, gaddr) \
    asm volatile("cp.async.cg.shared.global [%0], [%1], 16;" :: "r"(saddr), "l"(gaddr) : "memory")
#define CP_COMMIT() asm volatile("cp.async.commit_group;" ::: "memory")
#define CP_WAIT(n)  asm volatile("cp.async.wait_group %0;" :: "n"(n) : "memory")

#define LDMATRIX_X4(r0, r1, r2, r3, addr) \
    asm volatile("ldmatrix.sync.aligned.m8n8.x4.shared.b16 {%0,%1,%2,%3}, [%4];" \
                 : "=r"(r0), "=r"(r1), "=r"(r2), "=r"(r3) : "r"(addr))
#define LDMATRIX_X2(r0, r1, addr) \
    asm volatile("ldmatrix.sync.aligned.m8n8.x2.shared.b16 {%0,%1}, [%2];" \
                 : "=r"(r0), "=r"(r1) : "r"(addr))
#define MMA_BF16(d0, d1, d2, d3, a0, a1, a2, a3, b0, b1) \
    asm volatile("mma.sync.aligned.m16n8k16.row.col.f32.bf16.bf16.f32 " \
                 "{%0,%1,%2,%3}, {%4,%5,%6,%7}, {%8,%9}, {%0,%1,%2,%3};" \
                 : "+f"(d0), "+f"(d1), "+f"(d2), "+f"(d3) \
                 : "r"(a0), "r"(a1), "r"(a2), "r"(a3), "r"(b0), "r"(b1))

// Deterministic float atomic max (int/uint ordering trick)
__device__ __forceinline__ void atomicMaxF(float* addr, float v) {
    if (v >= 0.f) atomicMax((int*)addr, __float_as_int(v));
    else          atomicMin((unsigned int*)addr, __float_as_uint(v));
}

// ---------------------------------------------------------------------------
// K0: merged prep — wsplit (blocks 0..383), osplit (384..511), kinit (512..519)
// ---------------------------------------------------------------------------
__global__ __launch_bounds__(256) void k_prep(const float* __restrict__ wqkv,
                                              const float* __restrict__ gch,
                                              const float* __restrict__ wout,
                                              const float* __restrict__ memkv) {
    int blk = blockIdx.x;
    int tid = threadIdx.x;
    if (blk < 384) {
        int e = blk * 256 + tid;
        int k = e & 255;
        float w = wqkv[e] * gch[k];
        __nv_bfloat16 hi = __float2bfloat16(w);
        __nv_bfloat16 lo = __float2bfloat16(w - __bfloat162float(hi));
        g_wh[e] = hi;
        g_wl[e] = lo;
    } else if (blk < 512) {
        int e = (blk - 384) * 256 + tid;
        float w = wout[e];
        __nv_bfloat16 hi = __float2bfloat16(w);
        __nv_bfloat16 lo = __float2bfloat16(w - __bfloat162float(hi));
        g_woh[e] = hi;
        g_wol[e] = lo;
    } else {
        int idx = (blk - 512) * 256 + tid;    // b*128 + hd
        int hd = idx & 127;
        float mm = -INFINITY;
        #pragma unroll
        for (int j = 0; j < NMEM; j++) mm = fmaxf(mm, memkv[hd * NMEM + j]);
        g_kmax[idx] = mm;
    }
}

// ---------------------------------------------------------------------------
// K1: fused rnorm + transpose + bf16 split.  32-n tile: 34.9KB smem -> 6 CTAs/SM.
// ---------------------------------------------------------------------------
#define XP_NT  32
#define XP_PAD 33
#define XP_SMEM ((256 * XP_PAD + 8 * XP_NT + XP_NT) * 4)

__global__ __launch_bounds__(256) void k_xprep(const float* __restrict__ x) {
    extern __shared__ float xs[];
    float* red = xs + 256 * XP_PAD;   // [8][32]
    float* rns = red + 8 * XP_NT;     // [32]
    int n0 = blockIdx.x * XP_NT;
    int b  = blockIdx.y;
    int tid = threadIdx.x;
    const float* xb = x + (size_t)b * CDIM * NDIM + n0;

    #pragma unroll
    for (int t = 0; t < 8; t++) {
        int idx = tid + t * 256;
        int c = idx >> 3, nch = idx & 7;
        float4 v = *(const float4*)(xb + (size_t)c * NDIM + nch * 4);
        float* row = xs + c * XP_PAD + nch * 4;
        row[0] = v.x; row[1] = v.y; row[2] = v.z; row[3] = v.w;
    }
    __syncthreads();

    {
        int n = tid & 31, p = tid >> 5;
        const float* col = xs + (p * 32) * XP_PAD + n;
        float s = 0.f;
        #pragma unroll 8
        for (int i = 0; i < 32; i++) {
            float v = col[i * XP_PAD];
            s += v * v;
        }
        red[p * XP_NT + n] = s;
    }
    __syncthreads();
    if (tid < XP_NT) {
        float s = 0.f;
        #pragma unroll
        for (int p = 0; p < 8; p++) s += red[p * XP_NT + tid];
        rns[tid] = 16.0f / fmaxf(sqrtf(s), EPSN);
    }
    __syncthreads();

    #pragma unroll
    for (int t = 0; t < 16; t++) {
        int job = tid + t * 256;
        int cp = job & 127, n = job >> 7;
        float rn = rns[n];
        float v0 = xs[(2 * cp + 0) * XP_PAD + n] * rn;
        float v1 = xs[(2 * cp + 1) * XP_PAD + n] * rn;
        __nv_bfloat16 h0 = __float2bfloat16(v0);
        __nv_bfloat16 h1 = __float2bfloat16(v1);
        __nv_bfloat16 l0 = __float2bfloat16(v0 - __bfloat162float(h0));
        __nv_bfloat16 l1 = __float2bfloat16(v1 - __bfloat162float(h1));
        uint32_t hp = (uint32_t)*(uint16_t*)&h0 | ((uint32_t)*(uint16_t*)&h1 << 16);
        uint32_t lp = (uint32_t)*(uint16_t*)&l0 | ((uint32_t)*(uint16_t*)&l1 << 16);
        size_t o = ((size_t)b * NDIM + n0 + n) * CDIM + cp * 2;
        *(uint32_t*)&g_xh[o] = hp;
        *(uint32_t*)&g_xl[o] = lp;
    }
}

// ---------------------------------------------------------------------------
// K2: QKV GEMM via mma.sync bf16 (split-bf16, 3 terms).
// Epilogue atomicMax's K rows into g_kmax (blockIdx.x == 1).
// ---------------------------------------------------------------------------
#define RS 80
#define T_AH 0
#define T_AL 10240
#define T_BH 20480
#define T_BL 30720
#define STG  40960

__global__ __launch_bounds__(256) void k_qkv_mma() {
    extern __shared__ char smem[];
    uint32_t sb = smem_u32(smem);
    int tid = threadIdx.x;
    int lane = tid & 31, wid = tid >> 5;
    int wm = wid & 1, wn = wid >> 1;
    int m0 = blockIdx.x * 128;
    int n0 = blockIdx.y * 128;
    int b  = blockIdx.z;

    const __nv_bfloat16* xhb = g_xh + (size_t)b * NDIM * CDIM;
    const __nv_bfloat16* xlb = g_xl + (size_t)b * NDIM * CDIM;

    float acc[4][4][4];
    #pragma unroll
    for (int i = 0; i < 4; i++)
        #pragma unroll
        for (int j = 0; j < 4; j++)
            #pragma unroll
            for (int r = 0; r < 4; r++) acc[i][j][r] = 0.f;

    auto issue_stage = [&](int s) {
        int k0 = s * 32;
        uint32_t dst_base = sb + (s & 1) * STG;
        #pragma unroll
        for (int t = 0; t < 8; t++) {
            int idx = tid + t * 256;
            int tile = idx >> 9;
            int i = idx & 511;
            int row = i >> 2, pos = i & 3;
            uint32_t daddr = dst_base + tile * 10240 + row * RS + pos * 16;
            const __nv_bfloat16* src;
            if (tile == 0)      src = g_wh + (size_t)(m0 + row) * CDIM + k0 + pos * 8;
            else if (tile == 1) src = g_wl + (size_t)(m0 + row) * CDIM + k0 + pos * 8;
            else if (tile == 2) src = xhb + (size_t)(n0 + row) * CDIM + k0 + pos * 8;
            else                src = xlb + (size_t)(n0 + row) * CDIM + k0 + pos * 8;
            CP_ASYNC16(daddr, src);
        }
        CP_COMMIT();
    };

    issue_stage(0);
    for (int s = 0; s < 8; s++) {
        if (s + 1 < 8) {
            issue_stage(s + 1);
            CP_WAIT(1);
        } else {
            CP_WAIT(0);
        }
        __syncthreads();
        uint32_t buf = sb + (s & 1) * STG;

        #pragma unroll
        for (int ks = 0; ks < 2; ks++) {
            uint32_t ah[4][4], al[4][4], bh[4][2], bl[4][2];
            int akoff = (ks * 16 + (lane >> 4) * 8) * 2;
            int arow = (lane & 15);
            #pragma unroll
            for (int mi = 0; mi < 4; mi++) {
                int rb = wm * 64 + mi * 16 + arow;
                LDMATRIX_X4(ah[mi][0], ah[mi][1], ah[mi][2], ah[mi][3], buf + T_AH + rb * RS + akoff);
                LDMATRIX_X4(al[mi][0], al[mi][1], al[mi][2], al[mi][3], buf + T_AL + rb * RS + akoff);
            }
            int l = lane & 15;
            int bkoff = (ks * 16 + (l >> 3) * 8) * 2;
            int brow = l & 7;
            #pragma unroll
            for (int ni = 0; ni < 4; ni++) {
                int rb = wn * 32 + ni * 8 + brow;
                LDMATRIX_X2(bh[ni][0], bh[ni][1], buf + T_BH + rb * RS + bkoff);
                LDMATRIX_X2(bl[ni][0], bl[ni][1], buf + T_BL + rb * RS + bkoff);
            }
            #pragma unroll
            for (int mi = 0; mi < 4; mi++)
                #pragma unroll
                for (int ni = 0; ni < 4; ni++)
                    MMA_BF16(acc[mi][ni][0], acc[mi][ni][1], acc[mi][ni][2], acc[mi][ni][3],
                             ah[mi][0], ah[mi][1], ah[mi][2], ah[mi][3], bh[ni][0], bh[ni][1]);
            #pragma unroll
            for (int mi = 0; mi < 4; mi++)
                #pragma unroll
                for (int ni = 0; ni < 4; ni++)
                    MMA_BF16(acc[mi][ni][0], acc[mi][ni][1], acc[mi][ni][2], acc[mi][ni][3],
                             ah[mi][0], ah[mi][1], ah[mi][2], ah[mi][3], bl[ni][0], bl[ni][1]);
            #pragma unroll
            for (int mi = 0; mi < 4; mi++)
                #pragma unroll
                for (int ni = 0; ni < 4; ni++)
                    MMA_BF16(acc[mi][ni][0], acc[mi][ni][1], acc[mi][ni][2], acc[mi][ni][3],
                             al[mi][0], al[mi][1], al[mi][2], al[mi][3], bh[ni][0], bh[ni][1]);
        }
        __syncthreads();
    }

    float* outp = g_qkv + (size_t)b * QKVROWS * NDIM;
    int tr = lane >> 2, tc = (lane & 3) * 2;
    #pragma unroll
    for (int mi = 0; mi < 4; mi++) {
        #pragma unroll
        for (int ni = 0; ni < 4; ni++) {
            int o0 = m0 + wm * 64 + mi * 16 + tr;
            int nn = n0 + wn * 32 + ni * 8 + tc;
            float2 v0 = make_float2(acc[mi][ni][0], acc[mi][ni][1]);
            float2 v1 = make_float2(acc[mi][ni][2], acc[mi][ni][3]);
            *(float2*)(outp + (size_t)o0 * NDIM + nn)       = v0;
            *(float2*)(outp + (size_t)(o0 + 8) * NDIM + nn) = v1;
        }
    }

    if (blockIdx.x == 1) {
        #pragma unroll
        for (int mi = 0; mi < 4; mi++) {
            float mA = -INFINITY, mB = -INFINITY;
            #pragma unroll
            for (int ni = 0; ni < 4; ni++) {
                mA = fmaxf(mA, fmaxf(acc[mi][ni][0], acc[mi][ni][1]));
                mB = fmaxf(mB, fmaxf(acc[mi][ni][2], acc[mi][ni][3]));
            }
            mA = fmaxf(mA, __shfl_xor_sync(0xffffffffu, mA, 1));
            mA = fmaxf(mA, __shfl_xor_sync(0xffffffffu, mA, 2));
            mB = fmaxf(mB, __shfl_xor_sync(0xffffffffu, mB, 1));
            mB = fmaxf(mB, __shfl_xor_sync(0xffffffffu, mB, 2));
            if ((lane & 3) == 0) {
                int hd = wm * 64 + mi * 16 + tr;
                atomicMaxF(&g_kmax[b * 128 + hd], mA);
                atomicMaxF(&g_kmax[b * 128 + hd + 8], mB);
            }
        }
    }
}

// ---------------------------------------------------------------------------
// K3b (stage A): partial ctx over an n-chunk of 256, split 4-way in j.
// Transposed smem [j][36]: float4 inner-loop loads, conflict-free STS.128.
// ---------------------------------------------------------------------------
#define JP 36

__global__ __launch_bounds__(256) void k_ctx_part() {
    __shared__ float ks[128 * JP];
    __shared__ float vs[128 * JP];
    __shared__ float kml[32];
    int chunk = blockIdx.x;
    int bh = blockIdx.y;
    int b = bh >> 2, h = bh & 3;
    int tid = threadIdx.x;
    int jp = tid >> 6;
    int tile = tid & 63;
    int d0 = (tile & 7) * 4;
    int e0 = (tile >> 3) * 4;

    const float* base = g_qkv + (size_t)b * QKVROWS * NDIM;
    const float* kp = base + (size_t)(HID + h * ADIM) * NDIM;
    const float* vp = base + (size_t)(2 * HID + h * ADIM) * NDIM;

    if (tid < 32) kml[tid] = g_kmax[b * 128 + h * 32 + tid];
    __syncthreads();

    float acc[4][4];
    #pragma unroll
    for (int i = 0; i < 4; i++)
        #pragma unroll
        for (int m = 0; m < 4; m++) acc[i][m] = 0.f;
    float zacc[4] = {0.f, 0.f, 0.f, 0.f};

    for (int st = 0; st < 2; st++) {
        int n0 = chunk * 256 + st * 128;
        __syncthreads();
        // convert phase: thread owns (j=c, d-rows r4..r4+3); STS.128 conflict-free
        #pragma unroll
        for (int f = tid; f < 1024; f += 256) {
            int c = f & 127;            // j
            int r4 = (f >> 7) * 4;      // 0,4,...,28
            float4 ek, vv;
            ek.x = __expf(kp[(size_t)(r4 + 0) * NDIM + n0 + c] - kml[r4 + 0]);
            ek.y = __expf(kp[(size_t)(r4 + 1) * NDIM + n0 + c] - kml[r4 + 1]);
            ek.z = __expf(kp[(size_t)(r4 + 2) * NDIM + n0 + c] - kml[r4 + 2]);
            ek.w = __expf(kp[(size_t)(r4 + 3) * NDIM + n0 + c] - kml[r4 + 3]);
            vv.x = vp[(size_t)(r4 + 0) * NDIM + n0 + c];
            vv.y = vp[(size_t)(r4 + 1) * NDIM + n0 + c];
            vv.z = vp[(size_t)(r4 + 2) * NDIM + n0 + c];
            vv.w = vp[(size_t)(r4 + 3) * NDIM + n0 + c];
            *(float4*)&ks[c * JP + r4] = ek;
            *(float4*)&vs[c * JP + r4] = vv;
        }
        __syncthreads();
        #pragma unroll 4
        for (int jj = 0; jj < 32; jj++) {
            int j = jp * 32 + jj;
            float4 kd = *(const float4*)&ks[j * JP + d0];
            float4 vv = *(const float4*)&vs[j * JP + e0];
            float kda[4] = {kd.x, kd.y, kd.z, kd.w};
            float vva[4] = {vv.x, vv.y, vv.z, vv.w};
            #pragma unroll
            for (int i = 0; i < 4; i++)
                #pragma unroll
                for (int m = 0; m < 4; m++) acc[i][m] += kda[i] * vva[m];
            if (e0 == 0) {
                #pragma unroll
                for (int i = 0; i < 4; i++) zacc[i] += kda[i];
            }
        }
    }
    int pc = chunk * 4 + jp;
    float* pp = g_ctx_part + ((size_t)pc * 64 + bh) * 1024;
    #pragma unroll
    for (int i = 0; i < 4; i++) {
        float4 v = make_float4(acc[i][0], acc[i][1], acc[i][2], acc[i][3]);
        *(float4*)(pp + (d0 + i) * 32 + e0) = v;
    }
    if (e0 == 0) {
        float* zp = g_z_part + ((size_t)pc * 64 + bh) * 32;
        #pragma unroll
        for (int i = 0; i < 4; i++) zp[d0 + i] = zacc[i];
    }
}

// ---------------------------------------------------------------------------
// K3b (stage B): reduce NPART partials, add memory tokens, fold SCALE / Z.
// ---------------------------------------------------------------------------
__global__ __launch_bounds__(1024) void k_ctx_reduce(const float* __restrict__ memkv) {
    __shared__ float zs[32];
    int bh = blockIdx.x;
    int b = bh >> 2, h = bh & 3;
    int tid = threadIdx.x;
    int d = tid >> 5, e = tid & 31;

    float acc = 0.f;
    #pragma unroll 8
    for (int c = 0; c < NPART; c++)
        acc += g_ctx_part[((size_t)c * 64 + bh) * 1024 + tid];

    float km = g_kmax[b * 128 + h * 32 + d];
    const float* mk = memkv + h * 128 + d * NMEM;
    const float* mv = memkv + 512 + h * 128 + e * NMEM;
    float zmem = 0.f;
    #pragma unroll
    for (int j = 0; j < NMEM; j++) {
        float ek = __expf(mk[j] - km);
        acc += ek * mv[j];
        zmem += ek;
    }
    if (e == 0) {
        float z = zmem;
        #pragma unroll 8
        for (int c = 0; c < NPART; c++)
            z += g_z_part[((size_t)c * 64 + bh) * 32 + d];
        zs[d] = z;
    }
    __syncthreads();
    g_ctx[(size_t)bh * 1024 + tid] = acc * SCALE / zs[d];
}

// ---------------------------------------------------------------------------
// K4: fused epilogue, 64-col n-tile, register-lean for 2 CTAs/SM.
// ---------------------------------------------------------------------------
#define F_OSH  0
#define F_OSL  17408
#define F_WB0  34816
#define F_WB1  55296
#define F_CS   55296
#define FIN_SMEM 75776

__global__ __launch_bounds__(256, 2) void k_final_mma(const float* __restrict__ b_out,
                                                      const float* __restrict__ gout,
                                                      float* __restrict__ out) {
    extern __shared__ char smem[];
    uint32_t sb = smem_u32(smem);
    int tid = threadIdx.x;
    int lane = tid & 31, wid = tid >> 5;
    int wm = wid & 3, wn = wid >> 2;    // 4m x 2n warps; warp tile 64m x 32n
    int b = blockIdx.y;
    int n0 = blockIdx.x * 64;
    const float* qp = g_qkv + (size_t)b * QKVROWS * NDIM;

    auto w_stage = [&](int kc, int bufsel) {
        uint32_t dst = sb + F_WB0 + bufsel * 20480;
        #pragma unroll
        for (int t = 0; t < 4; t++) {
            int idx = tid + t * 256;          // 0..1023
            int r = idx >> 2, q = idx & 3;
            const __nv_bfloat16* src;
            uint32_t daddr;
            if (q < 2) {
                src = g_woh + r * HID + kc * 16 + q * 8;
                daddr = dst + r * 80 + q * 16;
            } else {
                src = g_wol + r * HID + kc * 16 + (q - 2) * 8;
                daddr = dst + r * 80 + 32 + (q - 2) * 16;
            }
            CP_ASYNC16(daddr, src);
        }
        CP_COMMIT();
    };
    w_stage(0, 0);

    float* cs = (float*)(smem + F_CS);
    #pragma unroll
    for (int t = 0; t < 4; t++) {
        int idx = tid + t * 256;
        *(float4*)(cs + idx * 4) = *(const float4*)(g_ctx + b * 4096 + idx * 4);
    }
    __syncthreads();

    {
        int h = tid >> 6, c = tid & 63;
        const float* colp = qp + (size_t)(h * 32) * NDIM + n0 + c;
        float qreg[32];
        float mx = -INFINITY;
        #pragma unroll
        for (int d = 0; d < 32; d++) { qreg[d] = colp[d * NDIM]; mx = fmaxf(mx, qreg[d]); }
        float s = 0.f;
        #pragma unroll
        for (int d = 0; d < 32; d++) { qreg[d] = __expf(qreg[d] - mx); s += qreg[d]; }
        float inv = 1.f / s;
        #pragma unroll
        for (int d = 0; d < 32; d++) qreg[d] *= inv;
        const float* ch = cs + h * 1024;
        #pragma unroll
        for (int e = 0; e < 32; e += 2) {
            float a0 = 0.f, a1 = 0.f;
            #pragma unroll
            for (int d = 0; d < 32; d++) {
                a0 += ch[d * 32 + e]     * qreg[d];
                a1 += ch[d * 32 + e + 1] * qreg[d];
            }
            __nv_bfloat16 h0 = __float2bfloat16(a0);
            __nv_bfloat16 h1 = __float2bfloat16(a1);
            __nv_bfloat16 l0 = __float2bfloat16(a0 - __bfloat162float(h0));
            __nv_bfloat16 l1 = __float2bfloat16(a1 - __bfloat162float(h1));
            uint32_t hp = (uint32_t)*(uint16_t*)&h0 | ((uint32_t)*(uint16_t*)&h1 << 16);
            uint32_t lp = (uint32_t)*(uint16_t*)&l0 | ((uint32_t)*(uint16_t*)&l1 << 16);
            uint32_t off = (uint32_t)c * 272 + (h * 32 + e) * 2;
            *(uint32_t*)(smem + F_OSH + off) = hp;
            *(uint32_t*)(smem + F_OSL + off) = lp;
        }
    }
    __syncthreads();
    w_stage(1, 1);            // cs dead; overwrite union region

    float acc[4][4][4];
    #pragma unroll
    for (int i = 0; i < 4; i++)
        #pragma unroll
        for (int j = 0; j < 4; j++)
            #pragma unroll
            for (int r = 0; r < 4; r++) acc[i][j][r] = 0.f;

    for (int kc = 0; kc < 8; kc++) {
        if (kc < 7) { CP_WAIT(1); } else { CP_WAIT(0); }
        __syncthreads();
        uint32_t wbuf = sb + F_WB0 + (kc & 1) * 20480;

        uint32_t bh[4][2], bl[4][2];
        int l = lane & 15;
        uint32_t bko = (uint32_t)(kc * 32 + (l >> 3) * 16);
        #pragma unroll
        for (int ni = 0; ni < 4; ni++) {
            uint32_t rb = wn * 32 + ni * 8 + (l & 7);
            uint32_t boff = rb * 272 + bko;
            LDMATRIX_X2(bh[ni][0], bh[ni][1], sb + F_OSH + boff);
            LDMATRIX_X2(bl[ni][0], bl[ni][1], sb + F_OSL + boff);
        }
        uint32_t ako = (uint32_t)((lane >> 4) * 16);
        #pragma unroll
        for (int mi = 0; mi < 4; mi++) {
            uint32_t ra = wm * 64 + mi * 16 + (lane & 15);
            uint32_t ah[4], al[4];
            LDMATRIX_X4(ah[0], ah[1], ah[2], ah[3], wbuf + ra * 80 + ako);
            LDMATRIX_X4(al[0], al[1], al[2], al[3], wbuf + ra * 80 + 32 + ako);
            #pragma unroll
            for (int ni = 0; ni < 4; ni++) {
                MMA_BF16(acc[mi][ni][0], acc[mi][ni][1], acc[mi][ni][2], acc[mi][ni][3],
                         ah[0], ah[1], ah[2], ah[3], bh[ni][0], bh[ni][1]);
                MMA_BF16(acc[mi][ni][0], acc[mi][ni][1], acc[mi][ni][2], acc[mi][ni][3],
                         ah[0], ah[1], ah[2], ah[3], bl[ni][0], bl[ni][1]);
                MMA_BF16(acc[mi][ni][0], acc[mi][ni][1], acc[mi][ni][2], acc[mi][ni][3],
                         al[0], al[1], al[2], al[3], bh[ni][0], bh[ni][1]);
            }
        }
        __syncthreads();
        if (kc + 2 < 8) w_stage(kc + 2, kc & 1);
    }

    int tr = lane >> 2, tc2 = (lane & 3) * 2;
    float bo[4][2], go[4][2];
    #pragma unroll
    for (int mi = 0; mi < 4; mi++) {
        int o = wm * 64 + mi * 16 + tr;
        bo[mi][0] = b_out[o];  bo[mi][1] = b_out[o + 8];
        go[mi][0] = gout[o];   go[mi][1] = gout[o + 8];
    }
    float* red = (float*)(smem + F_OSH);
    float* colsc = (float*)(smem + F_OSL);
    int rp = wm * 8 + tr;
    #pragma unroll
    for (int ni = 0; ni < 4; ni++) {
        float s0 = 0.f, s1 = 0.f;
        #pragma unroll
        for (int mi = 0; mi < 4; mi++) {
            float v0 = acc[mi][ni][0] + bo[mi][0];
            float v1 = acc[mi][ni][1] + bo[mi][0];
            float v2 = acc[mi][ni][2] + bo[mi][1];
            float v3 = acc[mi][ni][3] + bo[mi][1];
            acc[mi][ni][0] = v0; acc[mi][ni][1] = v1;
            acc[mi][ni][2] = v2; acc[mi][ni][3] = v3;
            s0 += v0 * v0 + v2 * v2;
            s1 += v1 * v1 + v3 * v3;
        }
        int col = wn * 32 + ni * 8 + tc2;
        red[col * 32 + rp]       = s0;
        red[(col + 1) * 32 + rp] = s1;
    }
    __syncthreads();
    if (tid < 64) {
        float s = 0.f;
        #pragma unroll 8
        for (int t = 0; t < 32; t++) s += red[tid * 32 + t];
        colsc[tid] = 16.0f / fmaxf(sqrtf(s), EPSN);
    }
    __syncthreads();

    float* ob = out + (size_t)b * CDIM * NDIM;
    #pragma unroll
    for (int mi = 0; mi < 4; mi++) {
        int o0 = wm * 64 + mi * 16 + tr;
        #pragma unroll
        for (int ni = 0; ni < 4; ni++) {
            int col = wn * 32 + ni * 8 + tc2;
            float sc0 = colsc[col], sc1 = colsc[col + 1];
            float2 v0 = make_float2(acc[mi][ni][0] * sc0 * go[mi][0],
                                    acc[mi][ni][1] * sc1 * go[mi][0]);
            float2 v1 = make_float2(acc[mi][ni][2] * sc0 * go[mi][1],
                                    acc[mi][ni][3] * sc1 * go[mi][1]);
            *(float2*)(ob + (size_t)o0 * NDIM + n0 + col)       = v0;
            *(float2*)(ob + (size_t)(o0 + 8) * NDIM + n0 + col) = v1;
        }
    }
}

// ---------------------------------------------------------------------------
extern "C" void kernel_launch(void* const* d_in, const int* in_sizes, int n_in,
                              void* d_out, int out_size) {
    const float* x      = (const float*)d_in[0];
    const float* norm_g = (const float*)d_in[1];
    const float* w_qkv  = (const float*)d_in[2];
    const float* mem_kv = (const float*)d_in[3];
    const float* w_out  = (const float*)d_in[4];
    const float* b_out  = (const float*)d_in[5];
    const float* out_g  = (const float*)d_in[6];
    float* out = (float*)d_out;

    k_prep<<<520, 256>>>(w_qkv, norm_g, w_out, mem_kv);

    cudaFuncSetAttribute(k_xprep, cudaFuncAttributeMaxDynamicSharedMemorySize, XP_SMEM);
    dim3 gx(NDIM / XP_NT, BATCH);
    k_xprep<<<gx, 256, XP_SMEM>>>(x);

    cudaFuncSetAttribute(k_qkv_mma, cudaFuncAttributeMaxDynamicSharedMemorySize, 2 * STG);
    dim3 g2(QKVROWS / 128, NDIM / 128, BATCH);
    k_qkv_mma<<<g2, 256, 2 * STG>>>();

    dim3 g3(NCHUNK, 64);
    k_ctx_part<<<g3, 256>>>();
    k_ctx_reduce<<<BATCH * HEADS, 1024>>>(mem_kv);

    cudaFuncSetAttribute(k_final_mma, cudaFuncAttributeMaxDynamicSharedMemorySize, FIN_SMEM);
    dim3 g4(NDIM / 64, BATCH);
    k_final_mma<<<g4, 256, FIN_SMEM>>>(b_out, out_g, out);
}

// round 17
// speedup vs baseline: 1.5488x; 1.0051x over previous
#include <cuda_runtime.h>
#include <cuda_bf16.h>
#include <math.h>
#include <stdint.h>

// Problem constants
#define BATCH 16
#define CDIM 256
#define NDIM 4096          // 64*64 spatial
#define HEADS 4
#define ADIM 32
#define HID 128
#define QKVROWS 384        // 3*HID
#define NMEM 4
#define SCALE 0.17677669529663687f   // 32^-0.5
#define EPSN 1e-12f
#define NCHUNK 16          // ctx n-chunks
#define NPART  64          // NCHUNK*4 partials

// Scratch (device globals: allocation-free per harness rules)
__device__ float g_qkv[(size_t)BATCH * QKVROWS * NDIM]; // ~100MB
__device__ float g_kmax[BATCH * HEADS * ADIM];
__device__ float g_ctx[BATCH * HEADS * ADIM * ADIM];    // already * SCALE / Z
__device__ float g_ctx_part[(size_t)NPART * 64 * 1024]; // 16MB partials
__device__ float g_z_part[NPART * 64 * 32];
// Pre-split bf16 operands (k-contiguous rows)
__device__ __nv_bfloat16 g_wh[QKVROWS * CDIM];
__device__ __nv_bfloat16 g_wl[QKVROWS * CDIM];
__device__ __nv_bfloat16 g_xh[(size_t)BATCH * NDIM * CDIM];  // [b][n][c]
__device__ __nv_bfloat16 g_xl[(size_t)BATCH * NDIM * CDIM];
// Pre-split w_out (256 x 128)
__device__ __nv_bfloat16 g_woh[CDIM * HID];
__device__ __nv_bfloat16 g_wol[CDIM * HID];

// ---------------------------------------------------------------------------
__device__ __forceinline__ uint32_t smem_u32(const void* p) {
    uint32_t a;
    asm("{ .reg .u64 t; cvta.to.shared.u64 t, %1; cvt.u32.u64 %0, t; }" : "=r"(a) : "l"(p));
    return a;
}
#define CP_ASYNC16(saddr, gaddr) \
    asm volatile("cp.async.cg.shared.global [%0], [%1], 16;" :: "r"(saddr), "l"(gaddr) : "memory")
#define CP_COMMIT() asm volatile("cp.async.commit_group;" ::: "memory")
#define CP_WAIT(n)  asm volatile("cp.async.wait_group %0;" :: "n"(n) : "memory")

#define LDMATRIX_X4(r0, r1, r2, r3, addr) \
    asm volatile("ldmatrix.sync.aligned.m8n8.x4.shared.b16 {%0,%1,%2,%3}, [%4];" \
                 : "=r"(r0), "=r"(r1), "=r"(r2), "=r"(r3) : "r"(addr))
#define LDMATRIX_X2(r0, r1, addr) \
    asm volatile("ldmatrix.sync.aligned.m8n8.x2.shared.b16 {%0,%1}, [%2];" \
                 : "=r"(r0), "=r"(r1) : "r"(addr))
#define MMA_BF16(d0, d1, d2, d3, a0, a1, a2, a3, b0, b1) \
    asm volatile("mma.sync.aligned.m16n8k16.row.col.f32.bf16.bf16.f32 " \
                 "{%0,%1,%2,%3}, {%4,%5,%6,%7}, {%8,%9}, {%0,%1,%2,%3};" \
                 : "+f"(d0), "+f"(d1), "+f"(d2), "+f"(d3) \
                 : "r"(a0), "r"(a1), "r"(a2), "r"(a3), "r"(b0), "r"(b1))

// Deterministic float atomic max (int/uint ordering trick)
__device__ __forceinline__ void atomicMaxF(float* addr, float v) {
    if (v >= 0.f) atomicMax((int*)addr, __float_as_int(v));
    else          atomicMin((unsigned int*)addr, __float_as_uint(v));
}

// ---------------------------------------------------------------------------
// K0: merged prep — wsplit (blocks 0..383), osplit (384..511), kinit (512..519)
// ---------------------------------------------------------------------------
__global__ __launch_bounds__(256) void k_prep(const float* __restrict__ wqkv,
                                              const float* __restrict__ gch,
                                              const float* __restrict__ wout,
                                              const float* __restrict__ memkv) {
    int blk = blockIdx.x;
    int tid = threadIdx.x;
    if (blk < 384) {
        int e = blk * 256 + tid;
        int k = e & 255;
        float w = wqkv[e] * gch[k];
        __nv_bfloat16 hi = __float2bfloat16(w);
        __nv_bfloat16 lo = __float2bfloat16(w - __bfloat162float(hi));
        g_wh[e] = hi;
        g_wl[e] = lo;
    } else if (blk < 512) {
        int e = (blk - 384) * 256 + tid;
        float w = wout[e];
        __nv_bfloat16 hi = __float2bfloat16(w);
        __nv_bfloat16 lo = __float2bfloat16(w - __bfloat162float(hi));
        g_woh[e] = hi;
        g_wol[e] = lo;
    } else {
        int idx = (blk - 512) * 256 + tid;    // b*128 + hd
        int hd = idx & 127;
        float mm = -INFINITY;
        #pragma unroll
        for (int j = 0; j < NMEM; j++) mm = fmaxf(mm, memkv[hd * NMEM + j]);
        g_kmax[idx] = mm;
    }
}

// ---------------------------------------------------------------------------
// K1: fused rnorm + transpose + bf16 split.  32-n tile: 34.9KB smem -> 6 CTAs/SM.
// ---------------------------------------------------------------------------
#define XP_NT  32
#define XP_PAD 33
#define XP_SMEM ((256 * XP_PAD + 8 * XP_NT + XP_NT) * 4)

__global__ __launch_bounds__(256) void k_xprep(const float* __restrict__ x) {
    extern __shared__ float xs[];
    float* red = xs + 256 * XP_PAD;   // [8][32]
    float* rns = red + 8 * XP_NT;     // [32]
    int n0 = blockIdx.x * XP_NT;
    int b  = blockIdx.y;
    int tid = threadIdx.x;
    const float* xb = x + (size_t)b * CDIM * NDIM + n0;

    #pragma unroll
    for (int t = 0; t < 8; t++) {
        int idx = tid + t * 256;
        int c = idx >> 3, nch = idx & 7;
        float4 v = *(const float4*)(xb + (size_t)c * NDIM + nch * 4);
        float* row = xs + c * XP_PAD + nch * 4;
        row[0] = v.x; row[1] = v.y; row[2] = v.z; row[3] = v.w;
    }
    __syncthreads();

    {
        int n = tid & 31, p = tid >> 5;
        const float* col = xs + (p * 32) * XP_PAD + n;
        float s = 0.f;
        #pragma unroll 8
        for (int i = 0; i < 32; i++) {
            float v = col[i * XP_PAD];
            s += v * v;
        }
        red[p * XP_NT + n] = s;
    }
    __syncthreads();
    if (tid < XP_NT) {
        float s = 0.f;
        #pragma unroll
        for (int p = 0; p < 8; p++) s += red[p * XP_NT + tid];
        rns[tid] = 16.0f / fmaxf(sqrtf(s), EPSN);
    }
    __syncthreads();

    #pragma unroll
    for (int t = 0; t < 16; t++) {
        int job = tid + t * 256;
        int cp = job & 127, n = job >> 7;
        float rn = rns[n];
        float v0 = xs[(2 * cp + 0) * XP_PAD + n] * rn;
        float v1 = xs[(2 * cp + 1) * XP_PAD + n] * rn;
        __nv_bfloat16 h0 = __float2bfloat16(v0);
        __nv_bfloat16 h1 = __float2bfloat16(v1);
        __nv_bfloat16 l0 = __float2bfloat16(v0 - __bfloat162float(h0));
        __nv_bfloat16 l1 = __float2bfloat16(v1 - __bfloat162float(h1));
        uint32_t hp = (uint32_t)*(uint16_t*)&h0 | ((uint32_t)*(uint16_t*)&h1 << 16);
        uint32_t lp = (uint32_t)*(uint16_t*)&l0 | ((uint32_t)*(uint16_t*)&l1 << 16);
        size_t o = ((size_t)b * NDIM + n0 + n) * CDIM + cp * 2;
        *(uint32_t*)&g_xh[o] = hp;
        *(uint32_t*)&g_xl[o] = lp;
    }
}

// ---------------------------------------------------------------------------
// K2: QKV GEMM via mma.sync bf16 (split-bf16, 3 terms).
// Epilogue atomicMax's K rows into g_kmax (blockIdx.x == 1).
// ---------------------------------------------------------------------------
#define RS 80
#define T_AH 0
#define T_AL 10240
#define T_BH 20480
#define T_BL 30720
#define STG  40960

__global__ __launch_bounds__(256) void k_qkv_mma() {
    extern __shared__ char smem[];
    uint32_t sb = smem_u32(smem);
    int tid = threadIdx.x;
    int lane = tid & 31, wid = tid >> 5;
    int wm = wid & 1, wn = wid >> 1;
    int m0 = blockIdx.x * 128;
    int n0 = blockIdx.y * 128;
    int b  = blockIdx.z;

    const __nv_bfloat16* xhb = g_xh + (size_t)b * NDIM * CDIM;
    const __nv_bfloat16* xlb = g_xl + (size_t)b * NDIM * CDIM;

    float acc[4][4][4];
    #pragma unroll
    for (int i = 0; i < 4; i++)
        #pragma unroll
        for (int j = 0; j < 4; j++)
            #pragma unroll
            for (int r = 0; r < 4; r++) acc[i][j][r] = 0.f;

    auto issue_stage = [&](int s) {
        int k0 = s * 32;
        uint32_t dst_base = sb + (s & 1) * STG;
        #pragma unroll
        for (int t = 0; t < 8; t++) {
            int idx = tid + t * 256;
            int tile = idx >> 9;
            int i = idx & 511;
            int row = i >> 2, pos = i & 3;
            uint32_t daddr = dst_base + tile * 10240 + row * RS + pos * 16;
            const __nv_bfloat16* src;
            if (tile == 0)      src = g_wh + (size_t)(m0 + row) * CDIM + k0 + pos * 8;
            else if (tile == 1) src = g_wl + (size_t)(m0 + row) * CDIM + k0 + pos * 8;
            else if (tile == 2) src = xhb + (size_t)(n0 + row) * CDIM + k0 + pos * 8;
            else                src = xlb + (size_t)(n0 + row) * CDIM + k0 + pos * 8;
            CP_ASYNC16(daddr, src);
        }
        CP_COMMIT();
    };

    issue_stage(0);
    for (int s = 0; s < 8; s++) {
        if (s + 1 < 8) {
            issue_stage(s + 1);
            CP_WAIT(1);
        } else {
            CP_WAIT(0);
        }
        __syncthreads();
        uint32_t buf = sb + (s & 1) * STG;

        #pragma unroll
        for (int ks = 0; ks < 2; ks++) {
            uint32_t ah[4][4], al[4][4], bh[4][2], bl[4][2];
            int akoff = (ks * 16 + (lane >> 4) * 8) * 2;
            int arow = (lane & 15);
            #pragma unroll
            for (int mi = 0; mi < 4; mi++) {
                int rb = wm * 64 + mi * 16 + arow;
                LDMATRIX_X4(ah[mi][0], ah[mi][1], ah[mi][2], ah[mi][3], buf + T_AH + rb * RS + akoff);
                LDMATRIX_X4(al[mi][0], al[mi][1], al[mi][2], al[mi][3], buf + T_AL + rb * RS + akoff);
            }
            int l = lane & 15;
            int bkoff = (ks * 16 + (l >> 3) * 8) * 2;
            int brow = l & 7;
            #pragma unroll
            for (int ni = 0; ni < 4; ni++) {
                int rb = wn * 32 + ni * 8 + brow;
                LDMATRIX_X2(bh[ni][0], bh[ni][1], buf + T_BH + rb * RS + bkoff);
                LDMATRIX_X2(bl[ni][0], bl[ni][1], buf + T_BL + rb * RS + bkoff);
            }
            #pragma unroll
            for (int mi = 0; mi < 4; mi++)
                #pragma unroll
                for (int ni = 0; ni < 4; ni++)
                    MMA_BF16(acc[mi][ni][0], acc[mi][ni][1], acc[mi][ni][2], acc[mi][ni][3],
                             ah[mi][0], ah[mi][1], ah[mi][2], ah[mi][3], bh[ni][0], bh[ni][1]);
            #pragma unroll
            for (int mi = 0; mi < 4; mi++)
                #pragma unroll
                for (int ni = 0; ni < 4; ni++)
                    MMA_BF16(acc[mi][ni][0], acc[mi][ni][1], acc[mi][ni][2], acc[mi][ni][3],
                             ah[mi][0], ah[mi][1], ah[mi][2], ah[mi][3], bl[ni][0], bl[ni][1]);
            #pragma unroll
            for (int mi = 0; mi < 4; mi++)
                #pragma unroll
                for (int ni = 0; ni < 4; ni++)
                    MMA_BF16(acc[mi][ni][0], acc[mi][ni][1], acc[mi][ni][2], acc[mi][ni][3],
                             al[mi][0], al[mi][1], al[mi][2], al[mi][3], bh[ni][0], bh[ni][1]);
        }
        __syncthreads();
    }

    float* outp = g_qkv + (size_t)b * QKVROWS * NDIM;
    int tr = lane >> 2, tc = (lane & 3) * 2;
    #pragma unroll
    for (int mi = 0; mi < 4; mi++) {
        #pragma unroll
        for (int ni = 0; ni < 4; ni++) {
            int o0 = m0 + wm * 64 + mi * 16 + tr;
            int nn = n0 + wn * 32 + ni * 8 + tc;
            float2 v0 = make_float2(acc[mi][ni][0], acc[mi][ni][1]);
            float2 v1 = make_float2(acc[mi][ni][2], acc[mi][ni][3]);
            *(float2*)(outp + (size_t)o0 * NDIM + nn)       = v0;
            *(float2*)(outp + (size_t)(o0 + 8) * NDIM + nn) = v1;
        }
    }

    if (blockIdx.x == 1) {
        #pragma unroll
        for (int mi = 0; mi < 4; mi++) {
            float mA = -INFINITY, mB = -INFINITY;
            #pragma unroll
            for (int ni = 0; ni < 4; ni++) {
                mA = fmaxf(mA, fmaxf(acc[mi][ni][0], acc[mi][ni][1]));
                mB = fmaxf(mB, fmaxf(acc[mi][ni][2], acc[mi][ni][3]));
            }
            mA = fmaxf(mA, __shfl_xor_sync(0xffffffffu, mA, 1));
            mA = fmaxf(mA, __shfl_xor_sync(0xffffffffu, mA, 2));
            mB = fmaxf(mB, __shfl_xor_sync(0xffffffffu, mB, 1));
            mB = fmaxf(mB, __shfl_xor_sync(0xffffffffu, mB, 2));
            if ((lane & 3) == 0) {
                int hd = wm * 64 + mi * 16 + tr;
                atomicMaxF(&g_kmax[b * 128 + hd], mA);
                atomicMaxF(&g_kmax[b * 128 + hd + 8], mB);
            }
        }
    }
}

// ---------------------------------------------------------------------------
// K3b (stage A): partial ctx over an n-chunk of 256, in 4 stages of 64 j.
// Transposed smem [j][36] (18.4KB total) + launch_bounds(256,5) for occupancy.
// ---------------------------------------------------------------------------
#define JP 36

__global__ __launch_bounds__(256, 5) void k_ctx_part() {
    __shared__ float ks[64 * JP];
    __shared__ float vs[64 * JP];
    __shared__ float kml[32];
    int chunk = blockIdx.x;
    int bh = blockIdx.y;
    int b = bh >> 2, h = bh & 3;
    int tid = threadIdx.x;
    int jp = tid >> 6;
    int tile = tid & 63;
    int d0 = (tile & 7) * 4;
    int e0 = (tile >> 3) * 4;

    const float* base = g_qkv + (size_t)b * QKVROWS * NDIM;
    const float* kp = base + (size_t)(HID + h * ADIM) * NDIM;
    const float* vp = base + (size_t)(2 * HID + h * ADIM) * NDIM;

    if (tid < 32) kml[tid] = g_kmax[b * 128 + h * 32 + tid];
    __syncthreads();

    float acc[4][4];
    #pragma unroll
    for (int i = 0; i < 4; i++)
        #pragma unroll
        for (int m = 0; m < 4; m++) acc[i][m] = 0.f;
    float zacc[4] = {0.f, 0.f, 0.f, 0.f};

    for (int st = 0; st < 4; st++) {
        int n0 = chunk * 256 + st * 64;
        __syncthreads();
        // convert phase: 512 jobs (c in 0..63, 8 d-groups); coalesced LDG,
        // conflict-free STS.128
        #pragma unroll
        for (int f = tid; f < 512; f += 256) {
            int c = f & 63;             // j
            int r4 = (f >> 6) * 4;      // 0,4,...,28
            float4 ek, vv;
            ek.x = __expf(kp[(size_t)(r4 + 0) * NDIM + n0 + c] - kml[r4 + 0]);
            ek.y = __expf(kp[(size_t)(r4 + 1) * NDIM + n0 + c] - kml[r4 + 1]);
            ek.z = __expf(kp[(size_t)(r4 + 2) * NDIM + n0 + c] - kml[r4 + 2]);
            ek.w = __expf(kp[(size_t)(r4 + 3) * NDIM + n0 + c] - kml[r4 + 3]);
            vv.x = vp[(size_t)(r4 + 0) * NDIM + n0 + c];
            vv.y = vp[(size_t)(r4 + 1) * NDIM + n0 + c];
            vv.z = vp[(size_t)(r4 + 2) * NDIM + n0 + c];
            vv.w = vp[(size_t)(r4 + 3) * NDIM + n0 + c];
            *(float4*)&ks[c * JP + r4] = ek;
            *(float4*)&vs[c * JP + r4] = vv;
        }
        __syncthreads();
        #pragma unroll 4
        for (int jj = 0; jj < 16; jj++) {
            int j = jp * 16 + jj;
            float4 kd = *(const float4*)&ks[j * JP + d0];
            float4 vv = *(const float4*)&vs[j * JP + e0];
            float kda[4] = {kd.x, kd.y, kd.z, kd.w};
            float vva[4] = {vv.x, vv.y, vv.z, vv.w};
            #pragma unroll
            for (int i = 0; i < 4; i++)
                #pragma unroll
                for (int m = 0; m < 4; m++) acc[i][m] += kda[i] * vva[m];
            if (e0 == 0) {
                #pragma unroll
                for (int i = 0; i < 4; i++) zacc[i] += kda[i];
            }
        }
    }
    int pc = chunk * 4 + jp;
    float* pp = g_ctx_part + ((size_t)pc * 64 + bh) * 1024;
    #pragma unroll
    for (int i = 0; i < 4; i++) {
        float4 v = make_float4(acc[i][0], acc[i][1], acc[i][2], acc[i][3]);
        *(float4*)(pp + (d0 + i) * 32 + e0) = v;
    }
    if (e0 == 0) {
        float* zp = g_z_part + ((size_t)pc * 64 + bh) * 32;
        #pragma unroll
        for (int i = 0; i < 4; i++) zp[d0 + i] = zacc[i];
    }
}

// ---------------------------------------------------------------------------
// K3b (stage B): reduce NPART partials, add memory tokens, fold SCALE / Z.
// ---------------------------------------------------------------------------
__global__ __launch_bounds__(1024) void k_ctx_reduce(const float* __restrict__ memkv) {
    __shared__ float zs[32];
    int bh = blockIdx.x;
    int b = bh >> 2, h = bh & 3;
    int tid = threadIdx.x;
    int d = tid >> 5, e = tid & 31;

    float acc = 0.f;
    #pragma unroll 8
    for (int c = 0; c < NPART; c++)
        acc += g_ctx_part[((size_t)c * 64 + bh) * 1024 + tid];

    float km = g_kmax[b * 128 + h * 32 + d];
    const float* mk = memkv + h * 128 + d * NMEM;
    const float* mv = memkv + 512 + h * 128 + e * NMEM;
    float zmem = 0.f;
    #pragma unroll
    for (int j = 0; j < NMEM; j++) {
        float ek = __expf(mk[j] - km);
        acc += ek * mv[j];
        zmem += ek;
    }
    if (e == 0) {
        float z = zmem;
        #pragma unroll 8
        for (int c = 0; c < NPART; c++)
            z += g_z_part[((size_t)c * 64 + bh) * 32 + d];
        zs[d] = z;
    }
    __syncthreads();
    g_ctx[(size_t)bh * 1024 + tid] = acc * SCALE / zs[d];
}

// ---------------------------------------------------------------------------
// K4: fused epilogue, 64-col n-tile, register-lean for 2 CTAs/SM.
// ---------------------------------------------------------------------------
#define F_OSH  0
#define F_OSL  17408
#define F_WB0  34816
#define F_WB1  55296
#define F_CS   55296
#define FIN_SMEM 75776

__global__ __launch_bounds__(256, 2) void k_final_mma(const float* __restrict__ b_out,
                                                      const float* __restrict__ gout,
                                                      float* __restrict__ out) {
    extern __shared__ char smem[];
    uint32_t sb = smem_u32(smem);
    int tid = threadIdx.x;
    int lane = tid & 31, wid = tid >> 5;
    int wm = wid & 3, wn = wid >> 2;    // 4m x 2n warps; warp tile 64m x 32n
    int b = blockIdx.y;
    int n0 = blockIdx.x * 64;
    const float* qp = g_qkv + (size_t)b * QKVROWS * NDIM;

    auto w_stage = [&](int kc, int bufsel) {
        uint32_t dst = sb + F_WB0 + bufsel * 20480;
        #pragma unroll
        for (int t = 0; t < 4; t++) {
            int idx = tid + t * 256;          // 0..1023
            int r = idx >> 2, q = idx & 3;
            const __nv_bfloat16* src;
            uint32_t daddr;
            if (q < 2) {
                src = g_woh + r * HID + kc * 16 + q * 8;
                daddr = dst + r * 80 + q * 16;
            } else {
                src = g_wol + r * HID + kc * 16 + (q - 2) * 8;
                daddr = dst + r * 80 + 32 + (q - 2) * 16;
            }
            CP_ASYNC16(daddr, src);
        }
        CP_COMMIT();
    };
    w_stage(0, 0);

    float* cs = (float*)(smem + F_CS);
    #pragma unroll
    for (int t = 0; t < 4; t++) {
        int idx = tid + t * 256;
        *(float4*)(cs + idx * 4) = *(const float4*)(g_ctx + b * 4096 + idx * 4);
    }
    __syncthreads();

    {
        int h = tid >> 6, c = tid & 63;
        const float* colp = qp + (size_t)(h * 32) * NDIM + n0 + c;
        float qreg[32];
        float mx = -INFINITY;
        #pragma unroll
        for (int d = 0; d < 32; d++) { qreg[d] = colp[d * NDIM]; mx = fmaxf(mx, qreg[d]); }
        float s = 0.f;
        #pragma unroll
        for (int d = 0; d < 32; d++) { qreg[d] = __expf(qreg[d] - mx); s += qreg[d]; }
        float inv = 1.f / s;
        #pragma unroll
        for (int d = 0; d < 32; d++) qreg[d] *= inv;
        const float* ch = cs + h * 1024;
        #pragma unroll
        for (int e = 0; e < 32; e += 2) {
            float a0 = 0.f, a1 = 0.f;
            #pragma unroll
            for (int d = 0; d < 32; d++) {
                a0 += ch[d * 32 + e]     * qreg[d];
                a1 += ch[d * 32 + e + 1] * qreg[d];
            }
            __nv_bfloat16 h0 = __float2bfloat16(a0);
            __nv_bfloat16 h1 = __float2bfloat16(a1);
            __nv_bfloat16 l0 = __float2bfloat16(a0 - __bfloat162float(h0));
            __nv_bfloat16 l1 = __float2bfloat16(a1 - __bfloat162float(h1));
            uint32_t hp = (uint32_t)*(uint16_t*)&h0 | ((uint32_t)*(uint16_t*)&h1 << 16);
            uint32_t lp = (uint32_t)*(uint16_t*)&l0 | ((uint32_t)*(uint16_t*)&l1 << 16);
            uint32_t off = (uint32_t)c * 272 + (h * 32 + e) * 2;
            *(uint32_t*)(smem + F_OSH + off) = hp;
            *(uint32_t*)(smem + F_OSL + off) = lp;
        }
    }
    __syncthreads();
    w_stage(1, 1);            // cs dead; overwrite union region

    float acc[4][4][4];
    #pragma unroll
    for (int i = 0; i < 4; i++)
        #pragma unroll
        for (int j = 0; j < 4; j++)
            #pragma unroll
            for (int r = 0; r < 4; r++) acc[i][j][r] = 0.f;

    for (int kc = 0; kc < 8; kc++) {
        if (kc < 7) { CP_WAIT(1); } else { CP_WAIT(0); }
        __syncthreads();
        uint32_t wbuf = sb + F_WB0 + (kc & 1) * 20480;

        uint32_t bh[4][2], bl[4][2];
        int l = lane & 15;
        uint32_t bko = (uint32_t)(kc * 32 + (l >> 3) * 16);
        #pragma unroll
        for (int ni = 0; ni < 4; ni++) {
            uint32_t rb = wn * 32 + ni * 8 + (l & 7);
            uint32_t boff = rb * 272 + bko;
            LDMATRIX_X2(bh[ni][0], bh[ni][1], sb + F_OSH + boff);
            LDMATRIX_X2(bl[ni][0], bl[ni][1], sb + F_OSL + boff);
        }
        uint32_t ako = (uint32_t)((lane >> 4) * 16);
        #pragma unroll
        for (int mi = 0; mi < 4; mi++) {
            uint32_t ra = wm * 64 + mi * 16 + (lane & 15);
            uint32_t ah[4], al[4];
            LDMATRIX_X4(ah[0], ah[1], ah[2], ah[3], wbuf + ra * 80 + ako);
            LDMATRIX_X4(al[0], al[1], al[2], al[3], wbuf + ra * 80 + 32 + ako);
            #pragma unroll
            for (int ni = 0; ni < 4; ni++) {
                MMA_BF16(acc[mi][ni][0], acc[mi][ni][1], acc[mi][ni][2], acc[mi][ni][3],
                         ah[0], ah[1], ah[2], ah[3], bh[ni][0], bh[ni][1]);
                MMA_BF16(acc[mi][ni][0], acc[mi][ni][1], acc[mi][ni][2], acc[mi][ni][3],
                         ah[0], ah[1], ah[2], ah[3], bl[ni][0], bl[ni][1]);
                MMA_BF16(acc[mi][ni][0], acc[mi][ni][1], acc[mi][ni][2], acc[mi][ni][3],
                         al[0], al[1], al[2], al[3], bh[ni][0], bh[ni][1]);
            }
        }
        __syncthreads();
        if (kc + 2 < 8) w_stage(kc + 2, kc & 1);
    }

    int tr = lane >> 2, tc2 = (lane & 3) * 2;
    float bo[4][2], go[4][2];
    #pragma unroll
    for (int mi = 0; mi < 4; mi++) {
        int o = wm * 64 + mi * 16 + tr;
        bo[mi][0] = b_out[o];  bo[mi][1] = b_out[o + 8];
        go[mi][0] = gout[o];   go[mi][1] = gout[o + 8];
    }
    float* red = (float*)(smem + F_OSH);
    float* colsc = (float*)(smem + F_OSL);
    int rp = wm * 8 + tr;
    #pragma unroll
    for (int ni = 0; ni < 4; ni++) {
        float s0 = 0.f, s1 = 0.f;
        #pragma unroll
        for (int mi = 0; mi < 4; mi++) {
            float v0 = acc[mi][ni][0] + bo[mi][0];
            float v1 = acc[mi][ni][1] + bo[mi][0];
            float v2 = acc[mi][ni][2] + bo[mi][1];
            float v3 = acc[mi][ni][3] + bo[mi][1];
            acc[mi][ni][0] = v0; acc[mi][ni][1] = v1;
            acc[mi][ni][2] = v2; acc[mi][ni][3] = v3;
            s0 += v0 * v0 + v2 * v2;
            s1 += v1 * v1 + v3 * v3;
        }
        int col = wn * 32 + ni * 8 + tc2;
        red[col * 32 + rp]       = s0;
        red[(col + 1) * 32 + rp] = s1;
    }
    __syncthreads();
    if (tid < 64) {
        float s = 0.f;
        #pragma unroll 8
        for (int t = 0; t < 32; t++) s += red[tid * 32 + t];
        colsc[tid] = 16.0f / fmaxf(sqrtf(s), EPSN);
    }
    __syncthreads();

    float* ob = out + (size_t)b * CDIM * NDIM;
    #pragma unroll
    for (int mi = 0; mi < 4; mi++) {
        int o0 = wm * 64 + mi * 16 + tr;
        #pragma unroll
        for (int ni = 0; ni < 4; ni++) {
            int col = wn * 32 + ni * 8 + tc2;
            float sc0 = colsc[col], sc1 = colsc[col + 1];
            float2 v0 = make_float2(acc[mi][ni][0] * sc0 * go[mi][0],
                                    acc[mi][ni][1] * sc1 * go[mi][0]);
            float2 v1 = make_float2(acc[mi][ni][2] * sc0 * go[mi][1],
                                    acc[mi][ni][3] * sc1 * go[mi][1]);
            *(float2*)(ob + (size_t)o0 * NDIM + n0 + col)       = v0;
            *(float2*)(ob + (size_t)(o0 + 8) * NDIM + n0 + col) = v1;
        }
    }
}

// ---------------------------------------------------------------------------
extern "C" void kernel_launch(void* const* d_in, const int* in_sizes, int n_in,
                              void* d_out, int out_size) {
    const float* x      = (const float*)d_in[0];
    const float* norm_g = (const float*)d_in[1];
    const float* w_qkv  = (const float*)d_in[2];
    const float* mem_kv = (const float*)d_in[3];
    const float* w_out  = (const float*)d_in[4];
    const float* b_out  = (const float*)d_in[5];
    const float* out_g  = (const float*)d_in[6];
    float* out = (float*)d_out;

    k_prep<<<520, 256>>>(w_qkv, norm_g, w_out, mem_kv);

    cudaFuncSetAttribute(k_xprep, cudaFuncAttributeMaxDynamicSharedMemorySize, XP_SMEM);
    dim3 gx(NDIM / XP_NT, BATCH);
    k_xprep<<<gx, 256, XP_SMEM>>>(x);

    cudaFuncSetAttribute(k_qkv_mma, cudaFuncAttributeMaxDynamicSharedMemorySize, 2 * STG);
    dim3 g2(QKVROWS / 128, NDIM / 128, BATCH);
    k_qkv_mma<<<g2, 256, 2 * STG>>>();

    dim3 g3(NCHUNK, 64);
    k_ctx_part<<<g3, 256>>>();
    k_ctx_reduce<<<BATCH * HEADS, 1024>>>(mem_kv);

    cudaFuncSetAttribute(k_final_mma, cudaFuncAttributeMaxDynamicSharedMemorySize, FIN_SMEM);
    dim3 g4(NDIM / 64, BATCH);
    k_final_mma<<<g4, 256, FIN_SMEM>>>(b_out, out_g, out);
}